// round 1
// baseline (speedup 1.0000x reference)
#include <cuda_runtime.h>
#include <cstddef>

// Problem constants
#define BB 2
#define NN 4096
#define DD 512
#define HH 8
#define DH 64
#define SCALE_F 0.125f   // 64^-0.5

// Scratch (allocation-free rule: __device__ globals)
__device__ float g_q[(size_t)BB * HH * NN * DH];      // [B,H,N,64]
__device__ float g_k[(size_t)BB * HH * NN * DH];
__device__ float g_v[(size_t)BB * HH * NN * DH];
__device__ float g_attn[(size_t)BB * NN * DD];        // [B,N,512]

// ---------------------------------------------------------------------------
// GEMM: C[M=8192, 512] = A[8192,512] @ W[512,512]^T
// tiles 64x64x16, 256 threads, 4x4 microtile per thread.
// ---------------------------------------------------------------------------

__global__ __launch_bounds__(256) void gemm_qkv_kernel(
    const float* __restrict__ x,
    const float* __restrict__ Wq,
    const float* __restrict__ Wk,
    const float* __restrict__ Wv)
{
    __shared__ float As[16][68];
    __shared__ float Bs[16][68];

    const float* W;
    float* out;
    if (blockIdx.z == 0)      { W = Wq; out = g_q; }
    else if (blockIdx.z == 1) { W = Wk; out = g_k; }
    else                      { W = Wv; out = g_v; }

    const int tid = threadIdx.x;
    const int m0 = blockIdx.y * 64;
    const int n0 = blockIdx.x * 64;
    const int tx = tid & 15;
    const int ty = tid >> 4;
    const int lr = tid >> 2;         // 0..63 tile row for loads
    const int lc = (tid & 3) * 4;    // 0,4,8,12 tile col (k) for loads

    float acc[4][4];
#pragma unroll
    for (int i = 0; i < 4; i++)
#pragma unroll
        for (int j = 0; j < 4; j++) acc[i][j] = 0.f;

    for (int k0 = 0; k0 < DD; k0 += 16) {
        float4 av = *(const float4*)(x + (size_t)(m0 + lr) * DD + k0 + lc);
        float4 bv = *(const float4*)(W + (size_t)(n0 + lr) * DD + k0 + lc);
        __syncthreads();
        As[lc + 0][lr] = av.x; As[lc + 1][lr] = av.y;
        As[lc + 2][lr] = av.z; As[lc + 3][lr] = av.w;
        Bs[lc + 0][lr] = bv.x; Bs[lc + 1][lr] = bv.y;
        Bs[lc + 2][lr] = bv.z; Bs[lc + 3][lr] = bv.w;
        __syncthreads();
#pragma unroll
        for (int kk = 0; kk < 16; kk++) {
            float4 a = *(const float4*)&As[kk][ty * 4];
            float4 b = *(const float4*)&Bs[kk][tx * 4];
            float ar[4] = {a.x, a.y, a.z, a.w};
            float br[4] = {b.x, b.y, b.z, b.w};
#pragma unroll
            for (int i = 0; i < 4; i++)
#pragma unroll
                for (int j = 0; j < 4; j++)
                    acc[i][j] += ar[i] * br[j];
        }
    }

    // write head-major: [B,H,N,64]
#pragma unroll
    for (int i = 0; i < 4; i++) {
        const int m = m0 + ty * 4 + i;
        const int b = m >> 12;
        const int n = m & (NN - 1);
#pragma unroll
        for (int j = 0; j < 4; j++) {
            const int o  = n0 + tx * 4 + j;
            const int h  = o >> 6;
            const int dd = o & 63;
            out[(((size_t)(b * HH + h) * NN) + n) * DH + dd] = acc[i][j];
        }
    }
}

__global__ __launch_bounds__(256) void gemm_out_kernel(
    const float* __restrict__ Wo,
    const float* __restrict__ bo,
    float* __restrict__ out)
{
    __shared__ float As[16][68];
    __shared__ float Bs[16][68];

    const float* A = g_attn;
    const int tid = threadIdx.x;
    const int m0 = blockIdx.y * 64;
    const int n0 = blockIdx.x * 64;
    const int tx = tid & 15;
    const int ty = tid >> 4;
    const int lr = tid >> 2;
    const int lc = (tid & 3) * 4;

    float acc[4][4];
#pragma unroll
    for (int i = 0; i < 4; i++)
#pragma unroll
        for (int j = 0; j < 4; j++) acc[i][j] = 0.f;

    for (int k0 = 0; k0 < DD; k0 += 16) {
        float4 av = *(const float4*)(A  + (size_t)(m0 + lr) * DD + k0 + lc);
        float4 bv = *(const float4*)(Wo + (size_t)(n0 + lr) * DD + k0 + lc);
        __syncthreads();
        As[lc + 0][lr] = av.x; As[lc + 1][lr] = av.y;
        As[lc + 2][lr] = av.z; As[lc + 3][lr] = av.w;
        Bs[lc + 0][lr] = bv.x; Bs[lc + 1][lr] = bv.y;
        Bs[lc + 2][lr] = bv.z; Bs[lc + 3][lr] = bv.w;
        __syncthreads();
#pragma unroll
        for (int kk = 0; kk < 16; kk++) {
            float4 a = *(const float4*)&As[kk][ty * 4];
            float4 b = *(const float4*)&Bs[kk][tx * 4];
            float ar[4] = {a.x, a.y, a.z, a.w};
            float br[4] = {b.x, b.y, b.z, b.w};
#pragma unroll
            for (int i = 0; i < 4; i++)
#pragma unroll
                for (int j = 0; j < 4; j++)
                    acc[i][j] += ar[i] * br[j];
        }
    }

#pragma unroll
    for (int i = 0; i < 4; i++) {
        const int m = m0 + ty * 4 + i;
#pragma unroll
        for (int j = 0; j < 4; j++) {
            const int o = n0 + tx * 4 + j;
            out[(size_t)m * DD + o] = acc[i][j] + bo[o];
        }
    }
}

// ---------------------------------------------------------------------------
// Flash attention: one query row per thread, K/V tiles of 64 keys via smem.
// grid (N/128, B*H), 128 threads.
// ---------------------------------------------------------------------------

__global__ __launch_bounds__(128) void attn_kernel()
{
    __shared__ float Ks[64 * DH];
    __shared__ float Vs[64 * DH];

    const int tid = threadIdx.x;
    const int bh  = blockIdx.y;
    const int row = blockIdx.x * 128 + tid;

    const float* qp = g_q + ((size_t)bh * NN + row) * DH;
    float q[DH];
#pragma unroll
    for (int i = 0; i < 16; i++) {
        float4 t = *(const float4*)(qp + i * 4);
        q[i * 4 + 0] = t.x * SCALE_F;
        q[i * 4 + 1] = t.y * SCALE_F;
        q[i * 4 + 2] = t.z * SCALE_F;
        q[i * 4 + 3] = t.w * SCALE_F;
    }

    float o[DH];
#pragma unroll
    for (int i = 0; i < DH; i++) o[i] = 0.f;
    float m = -1e30f;
    float l = 0.f;

    const float4* kbase = (const float4*)(g_k + (size_t)bh * NN * DH);
    const float4* vbase = (const float4*)(g_v + (size_t)bh * NN * DH);

    for (int t = 0; t < NN / 64; t++) {
        __syncthreads();
        const float4* ksrc = kbase + (size_t)t * (64 * DH / 4);
        const float4* vsrc = vbase + (size_t)t * (64 * DH / 4);
#pragma unroll
        for (int i = 0; i < 8; i++) {
            ((float4*)Ks)[tid + i * 128] = ksrc[tid + i * 128];
            ((float4*)Vs)[tid + i * 128] = vsrc[tid + i * 128];
        }
        __syncthreads();

#pragma unroll 1
        for (int c = 0; c < 4; c++) {
            float s[16];
#pragma unroll
            for (int jj = 0; jj < 16; jj++) {
                const float4* kr = (const float4*)(Ks + (c * 16 + jj) * DH);
                float a0 = 0.f, a1 = 0.f, a2 = 0.f, a3 = 0.f;
#pragma unroll
                for (int dd = 0; dd < 16; dd++) {
                    float4 kv = kr[dd];
                    a0 += q[dd * 4 + 0] * kv.x;
                    a1 += q[dd * 4 + 1] * kv.y;
                    a2 += q[dd * 4 + 2] * kv.z;
                    a3 += q[dd * 4 + 3] * kv.w;
                }
                s[jj] = (a0 + a1) + (a2 + a3);
            }

            float mt = m;
#pragma unroll
            for (int jj = 0; jj < 16; jj++) mt = fmaxf(mt, s[jj]);

            if (mt > m) {
                const float cf = __expf(m - mt);
                l *= cf;
#pragma unroll
                for (int dd = 0; dd < DH; dd++) o[dd] *= cf;
                m = mt;
            }

#pragma unroll
            for (int jj = 0; jj < 16; jj++) {
                const float p = __expf(s[jj] - m);
                l += p;
                const float4* vr = (const float4*)(Vs + (c * 16 + jj) * DH);
#pragma unroll
                for (int dd = 0; dd < 16; dd++) {
                    float4 vv = vr[dd];
                    o[dd * 4 + 0] += p * vv.x;
                    o[dd * 4 + 1] += p * vv.y;
                    o[dd * 4 + 2] += p * vv.z;
                    o[dd * 4 + 3] += p * vv.w;
                }
            }
        }
    }

    const float inv = 1.f / l;
    const int b = bh >> 3;
    const int h = bh & 7;
    float* op = g_attn + ((size_t)(b * NN + row)) * DD + h * DH;
#pragma unroll
    for (int i = 0; i < 16; i++) {
        float4 st;
        st.x = o[i * 4 + 0] * inv;
        st.y = o[i * 4 + 1] * inv;
        st.z = o[i * 4 + 2] * inv;
        st.w = o[i * 4 + 3] * inv;
        *(float4*)(op + i * 4) = st;
    }
}

// ---------------------------------------------------------------------------

extern "C" void kernel_launch(void* const* d_in, const int* in_sizes, int n_in,
                              void* d_out, int out_size)
{
    (void)in_sizes; (void)n_in; (void)out_size;
    const float* x  = (const float*)d_in[0];
    const float* Wq = (const float*)d_in[1];
    const float* Wk = (const float*)d_in[2];
    const float* Wv = (const float*)d_in[3];
    const float* Wo = (const float*)d_in[4];
    const float* bo = (const float*)d_in[5];
    float* out = (float*)d_out;

    // QKV projections (fused into one launch, z = q/k/v)
    gemm_qkv_kernel<<<dim3(DD / 64, (BB * NN) / 64, 3), 256>>>(x, Wq, Wk, Wv);
    // Flash attention
    attn_kernel<<<dim3(NN / 128, BB * HH), 128>>>();
    // Output projection + bias
    gemm_out_kernel<<<dim3(DD / 64, (BB * NN) / 64), 256>>>(Wo, bo, out);
}

// round 3
// speedup vs baseline: 2.0451x; 2.0451x over previous
#include <cuda_runtime.h>
#include <cstdint>
#include <cstddef>

// Problem constants
#define BB 2
#define NN 4096
#define DD 512
#define HH 8
#define DH 64
#define SCALE_F 0.125f   // 64^-0.5
#define LOG2E_F 1.4426950408889634f

// Scratch (allocation-free rule: __device__ globals)
__device__ float g_q[(size_t)BB * HH * NN * DH];      // [B,H,N,64]
__device__ float g_k[(size_t)BB * HH * NN * DH];
__device__ float g_v[(size_t)BB * HH * NN * DH];
__device__ float g_attn[(size_t)BB * NN * DD];        // [B,N,512]

// ===========================================================================
// Helpers (arch-neutral PTX only — harness compiles via compute_103, no 'a')
// ===========================================================================

__device__ __forceinline__ uint32_t f2tf32(float x) {
    uint32_t u;
    asm("cvt.rna.tf32.f32 %0, %1;" : "=r"(u) : "f"(x));
    return u;
}

__device__ __forceinline__ float ex2f(float x) {
    float y;
    asm("ex2.approx.ftz.f32 %0, %1;" : "=f"(y) : "f"(x));
    return y;
}

// D += A @ B   (m16n8k8, tf32 in, f32 accum)
__device__ __forceinline__ void mma_tf32(float* d, const uint32_t* a, const uint32_t* b) {
    asm volatile(
        "mma.sync.aligned.m16n8k8.row.col.f32.tf32.tf32.f32 "
        "{%0,%1,%2,%3}, {%4,%5,%6,%7}, {%8,%9}, {%0,%1,%2,%3};"
        : "+f"(d[0]), "+f"(d[1]), "+f"(d[2]), "+f"(d[3])
        : "r"(a[0]), "r"(a[1]), "r"(a[2]), "r"(a[3]), "r"(b[0]), "r"(b[1]));
}

// XOR-swizzled byte offset inside a [rows][64] fp32 tile (stride 64 floats).
// phys float4 index = row*16 + ((col/4) ^ (row & 15)); +4B elem within float4.
__device__ __forceinline__ uint32_t swz(uint32_t row, uint32_t col) {
    return ((row * 16u + ((col >> 2) ^ (row & 15u))) << 4) + ((col & 3u) << 2);
}

// ===========================================================================
// Flash attention with mma.sync tf32.
// CTA: 128 q rows of one (b,h), 8 warps (16 rows each), kv tiles of 64 keys.
// smem: sK [64][64] (key-major), sV [64][64] (dim-major = V^T), sP [128][64].
// ===========================================================================

#define SMK 0
#define SMV 16384
#define SMP 32768
#define SM_TOT 65536

__global__ void __launch_bounds__(256, 2) attn_mma_kernel()
{
    extern __shared__ char smem[];
    char* sK = smem + SMK;
    char* sV = smem + SMV;
    char* sP = smem + SMP;

    const int tid  = threadIdx.x;
    const int lane = tid & 31;
    const int warp = tid >> 5;
    const int bh   = blockIdx.y;
    const int q0   = blockIdx.x * 128;
    const int wrow = warp * 16;
    const int r0   = lane >> 2;     // 0..7
    const int cB   = lane & 3;      // 0..3

    const float* qg = g_q + ((size_t)bh * NN + q0) * DH;
    const float* kg = g_k + (size_t)bh * NN * DH;
    const float* vg = g_v + (size_t)bh * NN * DH;

    // ---- stage Q (prescaled to log2 domain, tf32) into sP ----
    {
        const int row = tid & 127;
        const int c0  = (tid >> 7) * 8;
        const float qs = SCALE_F * LOG2E_F;
        const float4* src = (const float4*)(qg + (size_t)row * DH);
#pragma unroll
        for (int i = 0; i < 8; i++) {
            float4 f = src[c0 + i];
            uint4 u;
            u.x = f2tf32(f.x * qs); u.y = f2tf32(f.y * qs);
            u.z = f2tf32(f.z * qs); u.w = f2tf32(f.w * qs);
            *(uint4*)(sP + (((uint32_t)row * 16u + (((uint32_t)(c0 + i)) ^ ((uint32_t)row & 15u))) << 4)) = u;
        }
    }
    __syncthreads();

    // Q A-fragments (registers, fixed for whole kernel)
    uint32_t qa[8][4];
#pragma unroll
    for (int k = 0; k < 8; k++) {
        const int rA = wrow + r0;
        qa[k][0] = *(const uint32_t*)(sP + swz(rA,     k * 8 + cB));
        qa[k][1] = *(const uint32_t*)(sP + swz(rA + 8, k * 8 + cB));
        qa[k][2] = *(const uint32_t*)(sP + swz(rA,     k * 8 + cB + 4));
        qa[k][3] = *(const uint32_t*)(sP + swz(rA + 8, k * 8 + cB + 4));
    }

    float o[8][4];
#pragma unroll
    for (int n = 0; n < 8; n++)
#pragma unroll
        for (int j = 0; j < 4; j++) o[n][j] = 0.f;
    float m0 = -1e30f, m1 = -1e30f, l0 = 0.f, l1 = 0.f;

    const int keyL = tid >> 2;  // 0..63
    const int fq   = tid & 3;

    for (int t = 0; t < NN / 64; t++) {
        __syncthreads();   // prior tile fully consumed (and, at t=0, qa loads done)

        // ---- load K tile [key][dim] (tf32, swizzled) ----
        {
            const float4* src = (const float4*)(kg + ((size_t)t * 64 + keyL) * DH);
#pragma unroll
            for (int i = 0; i < 4; i++) {
                const int c4 = fq + 4 * i;
                float4 f = src[c4];
                uint4 u;
                u.x = f2tf32(f.x); u.y = f2tf32(f.y);
                u.z = f2tf32(f.z); u.w = f2tf32(f.w);
                *(uint4*)(sK + (((uint32_t)keyL * 16u + (((uint32_t)c4) ^ ((uint32_t)keyL & 15u))) << 4)) = u;
            }
            // ---- load V tile transposed: sV[dim][key] ----
            const float4* vsrc = (const float4*)(vg + ((size_t)t * 64 + keyL) * DH);
#pragma unroll
            for (int i = 0; i < 4; i++) {
                const int c4 = fq + 4 * i;
                float4 f = vsrc[c4];
                *(uint32_t*)(sV + swz(c4 * 4 + 0, keyL)) = f2tf32(f.x);
                *(uint32_t*)(sV + swz(c4 * 4 + 1, keyL)) = f2tf32(f.y);
                *(uint32_t*)(sV + swz(c4 * 4 + 2, keyL)) = f2tf32(f.z);
                *(uint32_t*)(sV + swz(c4 * 4 + 3, keyL)) = f2tf32(f.w);
            }
        }
        __syncthreads();

        // ---- S = Q @ K^T  (16 x 64 per warp) ----
        float s[8][4];
#pragma unroll
        for (int n = 0; n < 8; n++)
#pragma unroll
            for (int j = 0; j < 4; j++) s[n][j] = 0.f;

#pragma unroll
        for (int k = 0; k < 8; k++) {
#pragma unroll
            for (int n = 0; n < 8; n++) {
                uint32_t b[2];
                b[0] = *(const uint32_t*)(sK + swz(n * 8 + r0, k * 8 + cB));
                b[1] = *(const uint32_t*)(sK + swz(n * 8 + r0, k * 8 + cB + 4));
                mma_tf32(s[n], qa[k], b);
            }
        }

        // ---- online softmax (log2 domain) ----
        float mx0 = -1e30f, mx1 = -1e30f;
#pragma unroll
        for (int n = 0; n < 8; n++) {
            mx0 = fmaxf(mx0, fmaxf(s[n][0], s[n][1]));
            mx1 = fmaxf(mx1, fmaxf(s[n][2], s[n][3]));
        }
        mx0 = fmaxf(mx0, __shfl_xor_sync(0xffffffffu, mx0, 1));
        mx0 = fmaxf(mx0, __shfl_xor_sync(0xffffffffu, mx0, 2));
        mx1 = fmaxf(mx1, __shfl_xor_sync(0xffffffffu, mx1, 1));
        mx1 = fmaxf(mx1, __shfl_xor_sync(0xffffffffu, mx1, 2));

        const float mn0 = fmaxf(m0, mx0);
        const float mn1 = fmaxf(m1, mx1);
        const float a0 = ex2f(m0 - mn0);
        const float a1 = ex2f(m1 - mn1);
        m0 = mn0; m1 = mn1;

        float sum0 = 0.f, sum1 = 0.f;
#pragma unroll
        for (int n = 0; n < 8; n++) {
            s[n][0] = ex2f(s[n][0] - m0);
            s[n][1] = ex2f(s[n][1] - m0);
            s[n][2] = ex2f(s[n][2] - m1);
            s[n][3] = ex2f(s[n][3] - m1);
            sum0 += s[n][0] + s[n][1];
            sum1 += s[n][2] + s[n][3];
        }
        sum0 += __shfl_xor_sync(0xffffffffu, sum0, 1);
        sum0 += __shfl_xor_sync(0xffffffffu, sum0, 2);
        sum1 += __shfl_xor_sync(0xffffffffu, sum1, 1);
        sum1 += __shfl_xor_sync(0xffffffffu, sum1, 2);
        l0 = l0 * a0 + sum0;
        l1 = l1 * a1 + sum1;

#pragma unroll
        for (int n = 0; n < 8; n++) {
            o[n][0] *= a0; o[n][1] *= a0;
            o[n][2] *= a1; o[n][3] *= a1;
        }

        // ---- P -> smem (C-frag layout -> re-read as A-frag) ----
#pragma unroll
        for (int n = 0; n < 8; n++) {
            const int col = n * 8 + 2 * cB;
            *(uint32_t*)(sP + swz(wrow + r0,     col))     = f2tf32(s[n][0]);
            *(uint32_t*)(sP + swz(wrow + r0,     col + 1)) = f2tf32(s[n][1]);
            *(uint32_t*)(sP + swz(wrow + r0 + 8, col))     = f2tf32(s[n][2]);
            *(uint32_t*)(sP + swz(wrow + r0 + 8, col + 1)) = f2tf32(s[n][3]);
        }
        __syncwarp();   // P rows are per-warp private; warp-level visibility suffices

        // ---- O += P @ V ----
#pragma unroll
        for (int k = 0; k < 8; k++) {
            uint32_t a[4];
            a[0] = *(const uint32_t*)(sP + swz(wrow + r0,     k * 8 + cB));
            a[1] = *(const uint32_t*)(sP + swz(wrow + r0 + 8, k * 8 + cB));
            a[2] = *(const uint32_t*)(sP + swz(wrow + r0,     k * 8 + cB + 4));
            a[3] = *(const uint32_t*)(sP + swz(wrow + r0 + 8, k * 8 + cB + 4));
#pragma unroll
            for (int n = 0; n < 8; n++) {
                uint32_t b[2];
                b[0] = *(const uint32_t*)(sV + swz(n * 8 + r0, k * 8 + cB));
                b[1] = *(const uint32_t*)(sV + swz(n * 8 + r0, k * 8 + cB + 4));
                mma_tf32(o[n], a, b);
            }
        }
    }

    // ---- epilogue: normalize, write g_attn[b, n, h*64 + :] ----
    const float inv0 = 1.f / l0;
    const float inv1 = 1.f / l1;
    const int b = bh >> 3, h = bh & 7;
    const int row0 = q0 + wrow + r0;
    float* out0 = g_attn + ((size_t)(b * NN + row0)) * DD + h * DH;
    float* out1 = out0 + (size_t)8 * DD;
#pragma unroll
    for (int n = 0; n < 8; n++) {
        const int col = n * 8 + 2 * cB;
        float2 v0; v0.x = o[n][0] * inv0; v0.y = o[n][1] * inv0;
        float2 v1; v1.x = o[n][2] * inv1; v1.y = o[n][3] * inv1;
        *(float2*)(out0 + col) = v0;
        *(float2*)(out1 + col) = v1;
    }
}

// ===========================================================================
// Scalar projection GEMMs (known good from R1)
// ===========================================================================

__global__ __launch_bounds__(256) void gemm_qkv_kernel(
    const float* __restrict__ x,
    const float* __restrict__ Wq,
    const float* __restrict__ Wk,
    const float* __restrict__ Wv)
{
    __shared__ float As[16][68];
    __shared__ float Bs[16][68];

    const float* W;
    float* out;
    if (blockIdx.z == 0)      { W = Wq; out = g_q; }
    else if (blockIdx.z == 1) { W = Wk; out = g_k; }
    else                      { W = Wv; out = g_v; }

    const int tid = threadIdx.x;
    const int m0 = blockIdx.y * 64;
    const int n0 = blockIdx.x * 64;
    const int tx = tid & 15;
    const int ty = tid >> 4;
    const int lr = tid >> 2;
    const int lc = (tid & 3) * 4;

    float acc[4][4];
#pragma unroll
    for (int i = 0; i < 4; i++)
#pragma unroll
        for (int j = 0; j < 4; j++) acc[i][j] = 0.f;

    for (int k0 = 0; k0 < DD; k0 += 16) {
        float4 av = *(const float4*)(x + (size_t)(m0 + lr) * DD + k0 + lc);
        float4 bv = *(const float4*)(W + (size_t)(n0 + lr) * DD + k0 + lc);
        __syncthreads();
        As[lc + 0][lr] = av.x; As[lc + 1][lr] = av.y;
        As[lc + 2][lr] = av.z; As[lc + 3][lr] = av.w;
        Bs[lc + 0][lr] = bv.x; Bs[lc + 1][lr] = bv.y;
        Bs[lc + 2][lr] = bv.z; Bs[lc + 3][lr] = bv.w;
        __syncthreads();
#pragma unroll
        for (int kk = 0; kk < 16; kk++) {
            float4 a = *(const float4*)&As[kk][ty * 4];
            float4 b = *(const float4*)&Bs[kk][tx * 4];
            float ar[4] = {a.x, a.y, a.z, a.w};
            float br[4] = {b.x, b.y, b.z, b.w};
#pragma unroll
            for (int i = 0; i < 4; i++)
#pragma unroll
                for (int j = 0; j < 4; j++)
                    acc[i][j] += ar[i] * br[j];
        }
    }

#pragma unroll
    for (int i = 0; i < 4; i++) {
        const int mm = m0 + ty * 4 + i;
        const int b = mm >> 12;
        const int n = mm & (NN - 1);
#pragma unroll
        for (int j = 0; j < 4; j++) {
            const int oo = n0 + tx * 4 + j;
            const int h  = oo >> 6;
            const int dd = oo & 63;
            out[(((size_t)(b * HH + h) * NN) + n) * DH + dd] = acc[i][j];
        }
    }
}

__global__ __launch_bounds__(256) void gemm_out_kernel(
    const float* __restrict__ Wo,
    const float* __restrict__ bo,
    float* __restrict__ out)
{
    __shared__ float As[16][68];
    __shared__ float Bs[16][68];

    const float* A = g_attn;
    const int tid = threadIdx.x;
    const int m0 = blockIdx.y * 64;
    const int n0 = blockIdx.x * 64;
    const int tx = tid & 15;
    const int ty = tid >> 4;
    const int lr = tid >> 2;
    const int lc = (tid & 3) * 4;

    float acc[4][4];
#pragma unroll
    for (int i = 0; i < 4; i++)
#pragma unroll
        for (int j = 0; j < 4; j++) acc[i][j] = 0.f;

    for (int k0 = 0; k0 < DD; k0 += 16) {
        float4 av = *(const float4*)(A  + (size_t)(m0 + lr) * DD + k0 + lc);
        float4 bv = *(const float4*)(Wo + (size_t)(n0 + lr) * DD + k0 + lc);
        __syncthreads();
        As[lc + 0][lr] = av.x; As[lc + 1][lr] = av.y;
        As[lc + 2][lr] = av.z; As[lc + 3][lr] = av.w;
        Bs[lc + 0][lr] = bv.x; Bs[lc + 1][lr] = bv.y;
        Bs[lc + 2][lr] = bv.z; Bs[lc + 3][lr] = bv.w;
        __syncthreads();
#pragma unroll
        for (int kk = 0; kk < 16; kk++) {
            float4 a = *(const float4*)&As[kk][ty * 4];
            float4 b = *(const float4*)&Bs[kk][tx * 4];
            float ar[4] = {a.x, a.y, a.z, a.w};
            float br[4] = {b.x, b.y, b.z, b.w};
#pragma unroll
            for (int i = 0; i < 4; i++)
#pragma unroll
                for (int j = 0; j < 4; j++)
                    acc[i][j] += ar[i] * br[j];
        }
    }

#pragma unroll
    for (int i = 0; i < 4; i++) {
        const int mm = m0 + ty * 4 + i;
#pragma unroll
        for (int j = 0; j < 4; j++) {
            const int oo = n0 + tx * 4 + j;
            out[(size_t)mm * DD + oo] = acc[i][j] + bo[oo];
        }
    }
}

// ===========================================================================

extern "C" void kernel_launch(void* const* d_in, const int* in_sizes, int n_in,
                              void* d_out, int out_size)
{
    (void)in_sizes; (void)n_in; (void)out_size;
    const float* x  = (const float*)d_in[0];
    const float* Wq = (const float*)d_in[1];
    const float* Wk = (const float*)d_in[2];
    const float* Wv = (const float*)d_in[3];
    const float* Wo = (const float*)d_in[4];
    const float* bo = (const float*)d_in[5];
    float* out = (float*)d_out;

    cudaFuncSetAttribute(attn_mma_kernel,
                         cudaFuncAttributeMaxDynamicSharedMemorySize, SM_TOT);

    gemm_qkv_kernel<<<dim3(DD / 64, (BB * NN) / 64, 3), 256>>>(x, Wq, Wk, Wv);
    attn_mma_kernel<<<dim3(NN / 128, BB * HH), 256, SM_TOT>>>();
    gemm_out_kernel<<<dim3(DD / 64, (BB * NN) / 64), 256>>>(Wo, bo, out);
}

// round 4
// speedup vs baseline: 2.0900x; 1.0220x over previous
#include <cuda_runtime.h>
#include <cstdint>
#include <cstddef>

// Problem constants
#define BB 2
#define NN 4096
#define DD 512
#define HH 8
#define DH 64
#define SCALE_F 0.125f   // 64^-0.5
#define LOG2E_F 1.4426950408889634f

// Scratch (allocation-free rule: __device__ globals)
// g_q: [B*H][N][64]  tf32 bits, pre-scaled by SCALE*LOG2E
// g_k: [B*H][N][64]  tf32 bits
// g_vt:[B*H][64][N]  tf32 bits (V transposed)
__device__ float g_q [(size_t)BB * HH * NN * DH];
__device__ float g_k [(size_t)BB * HH * NN * DH];
__device__ float g_vt[(size_t)BB * HH * NN * DH];
__device__ float g_attn[(size_t)BB * NN * DD];        // [B,N,512]

// ===========================================================================
// Helpers (arch-neutral PTX only — harness compiles via compute_103, no 'a')
// ===========================================================================

__device__ __forceinline__ uint32_t smem_u32(const void* p) {
    uint32_t a;
    asm("{ .reg .u64 t; cvta.to.shared.u64 t, %1; cvt.u32.u64 %0, t; }"
        : "=r"(a) : "l"(p));
    return a;
}

__device__ __forceinline__ uint32_t f2tf32(float x) {
    uint32_t u;
    asm("cvt.rna.tf32.f32 %0, %1;" : "=r"(u) : "f"(x));
    return u;
}

__device__ __forceinline__ float ex2f(float x) {
    float y;
    asm("ex2.approx.ftz.f32 %0, %1;" : "=f"(y) : "f"(x));
    return y;
}

// D += A @ B   (m16n8k8, tf32 in, f32 accum)
__device__ __forceinline__ void mma_tf32(float* d, const uint32_t* a, const uint32_t* b) {
    asm volatile(
        "mma.sync.aligned.m16n8k8.row.col.f32.tf32.tf32.f32 "
        "{%0,%1,%2,%3}, {%4,%5,%6,%7}, {%8,%9}, {%0,%1,%2,%3};"
        : "+f"(d[0]), "+f"(d[1]), "+f"(d[2]), "+f"(d[3])
        : "r"(a[0]), "r"(a[1]), "r"(a[2]), "r"(a[3]), "r"(b[0]), "r"(b[1]));
}

__device__ __forceinline__ void cp_async16(uint32_t dst, const void* src) {
    asm volatile("cp.async.cg.shared.global [%0], [%1], 16;"
                 :: "r"(dst), "l"(src) : "memory");
}
#define CP_COMMIT() asm volatile("cp.async.commit_group;" ::: "memory")
#define CP_WAIT0()  asm volatile("cp.async.wait_group 0;" ::: "memory")

// XOR-swizzled byte offset inside a [rows][64] fp32 tile (stride 64 floats).
__device__ __forceinline__ uint32_t swz(uint32_t row, uint32_t col) {
    return ((row * 16u + ((col >> 2) ^ (row & 15u))) << 4) + ((col & 3u) << 2);
}
// swizzled offset of a whole 16B chunk (row, col4 = col/4)
__device__ __forceinline__ uint32_t swz16(uint32_t row, uint32_t col4) {
    return (row * 16u + (col4 ^ (row & 15u))) << 4;
}

// ===========================================================================
// Flash attention, mma.sync tf32, cp.async double-buffered K/V^T tiles.
// CTA: 128 q rows of one (b,h), 8 warps (16 rows each), kv tiles of 64 keys.
// smem: sK[2][64][64], sVT[2][64][64], sP[128][64]  = 96KB
// ===========================================================================

#define SMK 0
#define SMV 32768
#define SMP 65536
#define SM_TOT 98304

__global__ void __launch_bounds__(256, 2) attn_mma_kernel()
{
    extern __shared__ char smem[];
    const uint32_t sbase = smem_u32(smem);
    char* sP = smem + SMP;

    const int tid  = threadIdx.x;
    const int lane = tid & 31;
    const int warp = tid >> 5;
    const int bh   = blockIdx.y;
    const int q0   = blockIdx.x * 128;
    const int wrow = warp * 16;
    const int r0   = lane >> 2;     // 0..7
    const int cB   = lane & 3;      // 0..3

    const float* qg  = g_q  + ((size_t)bh * NN + q0) * DH;
    const float* kg  = g_k  + (size_t)bh * NN * DH;
    const float* vtg = g_vt + (size_t)bh * NN * DH;   // [64][4096]

    const int rowL = tid >> 2;      // 0..63
    const int fq   = tid & 3;

    // ---- prologue: issue tile 0, load Q A-fragments directly (pre-converted) ----
    {
        const char* ksrc = (const char*)(kg + (size_t)rowL * DH) + fq * 16;
        const char* vsrc = (const char*)(vtg + (size_t)rowL * NN) + fq * 16;
        const uint32_t kdst = sbase + SMK;
        const uint32_t vdst = sbase + SMV;
#pragma unroll
        for (int i = 0; i < 4; i++) {
            const uint32_t c4 = (uint32_t)(fq + 4 * i);
            cp_async16(kdst + swz16((uint32_t)rowL, c4), ksrc + i * 64);
            cp_async16(vdst + swz16((uint32_t)rowL, c4), vsrc + i * 64);
        }
        CP_COMMIT();
    }

    uint32_t qa[8][4];
#pragma unroll
    for (int k = 0; k < 8; k++) {
        const float* qr = qg + (size_t)(wrow + r0) * DH + k * 8 + cB;
        qa[k][0] = __float_as_uint(qr[0]);
        qa[k][1] = __float_as_uint(qr[8 * DH]);
        qa[k][2] = __float_as_uint(qr[4]);
        qa[k][3] = __float_as_uint(qr[8 * DH + 4]);
    }

    float o[8][4];
#pragma unroll
    for (int n = 0; n < 8; n++)
#pragma unroll
        for (int j = 0; j < 4; j++) o[n][j] = 0.f;
    float m0 = -1e30f, m1 = -1e30f, l0 = 0.f, l1 = 0.f;

    for (int t = 0; t < NN / 64; t++) {
        CP_WAIT0();
        __syncthreads();          // tile t visible to all; all warps done with t-1

        // issue tile t+1 into the other buffer (overlaps with compute below)
        if (t + 1 < NN / 64) {
            const int buf = (t + 1) & 1;
            const char* ksrc = (const char*)(kg + ((size_t)(t + 1) * 64 + rowL) * DH) + fq * 16;
            const char* vsrc = (const char*)(vtg + (size_t)rowL * NN + (t + 1) * 64) + fq * 16;
            const uint32_t kdst = sbase + SMK + buf * 16384;
            const uint32_t vdst = sbase + SMV + buf * 16384;
#pragma unroll
            for (int i = 0; i < 4; i++) {
                const uint32_t c4 = (uint32_t)(fq + 4 * i);
                cp_async16(kdst + swz16((uint32_t)rowL, c4), ksrc + i * 64);
                cp_async16(vdst + swz16((uint32_t)rowL, c4), vsrc + i * 64);
            }
            CP_COMMIT();
        }

        char* sK = smem + SMK + (t & 1) * 16384;
        char* sV = smem + SMV + (t & 1) * 16384;

        // ---- S = Q @ K^T  (16 x 64 per warp) ----
        float s[8][4];
#pragma unroll
        for (int n = 0; n < 8; n++)
#pragma unroll
            for (int j = 0; j < 4; j++) s[n][j] = 0.f;

#pragma unroll
        for (int k = 0; k < 8; k++) {
#pragma unroll
            for (int n = 0; n < 8; n++) {
                uint32_t b[2];
                b[0] = *(const uint32_t*)(sK + swz(n * 8 + r0, k * 8 + cB));
                b[1] = *(const uint32_t*)(sK + swz(n * 8 + r0, k * 8 + cB + 4));
                mma_tf32(s[n], qa[k], b);
            }
        }

        // ---- online softmax (log2 domain) ----
        float mx0 = -1e30f, mx1 = -1e30f;
#pragma unroll
        for (int n = 0; n < 8; n++) {
            mx0 = fmaxf(mx0, fmaxf(s[n][0], s[n][1]));
            mx1 = fmaxf(mx1, fmaxf(s[n][2], s[n][3]));
        }
        mx0 = fmaxf(mx0, __shfl_xor_sync(0xffffffffu, mx0, 1));
        mx0 = fmaxf(mx0, __shfl_xor_sync(0xffffffffu, mx0, 2));
        mx1 = fmaxf(mx1, __shfl_xor_sync(0xffffffffu, mx1, 1));
        mx1 = fmaxf(mx1, __shfl_xor_sync(0xffffffffu, mx1, 2));

        const float mn0 = fmaxf(m0, mx0);
        const float mn1 = fmaxf(m1, mx1);
        const float a0 = ex2f(m0 - mn0);
        const float a1 = ex2f(m1 - mn1);
        m0 = mn0; m1 = mn1;

        float sum0 = 0.f, sum1 = 0.f;
#pragma unroll
        for (int n = 0; n < 8; n++) {
            s[n][0] = ex2f(s[n][0] - m0);
            s[n][1] = ex2f(s[n][1] - m0);
            s[n][2] = ex2f(s[n][2] - m1);
            s[n][3] = ex2f(s[n][3] - m1);
            sum0 += s[n][0] + s[n][1];
            sum1 += s[n][2] + s[n][3];
        }
        sum0 += __shfl_xor_sync(0xffffffffu, sum0, 1);
        sum0 += __shfl_xor_sync(0xffffffffu, sum0, 2);
        sum1 += __shfl_xor_sync(0xffffffffu, sum1, 1);
        sum1 += __shfl_xor_sync(0xffffffffu, sum1, 2);
        l0 = l0 * a0 + sum0;
        l1 = l1 * a1 + sum1;

#pragma unroll
        for (int n = 0; n < 8; n++) {
            o[n][0] *= a0; o[n][1] *= a0;
            o[n][2] *= a1; o[n][3] *= a1;
        }

        // ---- P -> smem (raw f32 bits; HMMA reads tf32 subset = truncation) ----
#pragma unroll
        for (int n = 0; n < 8; n++) {
            const int col = n * 8 + 2 * cB;
            *(uint32_t*)(sP + swz(wrow + r0,     col))     = __float_as_uint(s[n][0]);
            *(uint32_t*)(sP + swz(wrow + r0,     col + 1)) = __float_as_uint(s[n][1]);
            *(uint32_t*)(sP + swz(wrow + r0 + 8, col))     = __float_as_uint(s[n][2]);
            *(uint32_t*)(sP + swz(wrow + r0 + 8, col + 1)) = __float_as_uint(s[n][3]);
        }
        __syncwarp();   // P rows are per-warp private

        // ---- O += P @ V ----
#pragma unroll
        for (int k = 0; k < 8; k++) {
            uint32_t a[4];
            a[0] = *(const uint32_t*)(sP + swz(wrow + r0,     k * 8 + cB));
            a[1] = *(const uint32_t*)(sP + swz(wrow + r0 + 8, k * 8 + cB));
            a[2] = *(const uint32_t*)(sP + swz(wrow + r0,     k * 8 + cB + 4));
            a[3] = *(const uint32_t*)(sP + swz(wrow + r0 + 8, k * 8 + cB + 4));
#pragma unroll
            for (int n = 0; n < 8; n++) {
                uint32_t b[2];
                b[0] = *(const uint32_t*)(sV + swz(n * 8 + r0, k * 8 + cB));
                b[1] = *(const uint32_t*)(sV + swz(n * 8 + r0, k * 8 + cB + 4));
                mma_tf32(o[n], a, b);
            }
        }
    }

    // ---- epilogue: normalize, write g_attn[b, n, h*64 + :] ----
    const float inv0 = 1.f / l0;
    const float inv1 = 1.f / l1;
    const int b = bh >> 3, h = bh & 7;
    const int row0 = q0 + wrow + r0;
    float* out0 = g_attn + ((size_t)(b * NN + row0)) * DD + h * DH;
    float* out1 = out0 + (size_t)8 * DD;
#pragma unroll
    for (int n = 0; n < 8; n++) {
        const int col = n * 8 + 2 * cB;
        float2 v0; v0.x = o[n][0] * inv0; v0.y = o[n][1] * inv0;
        float2 v1; v1.x = o[n][2] * inv1; v1.y = o[n][3] * inv1;
        *(float2*)(out0 + col) = v0;
        *(float2*)(out1 + col) = v1;
    }
}

// ===========================================================================
// Scalar projection GEMMs. qkv epilogue now emits tf32 (Q pre-scaled, V^T).
// ===========================================================================

__global__ __launch_bounds__(256) void gemm_qkv_kernel(
    const float* __restrict__ x,
    const float* __restrict__ Wq,
    const float* __restrict__ Wk,
    const float* __restrict__ Wv)
{
    __shared__ float As[16][68];
    __shared__ float Bs[16][68];

    const float* W;
    if (blockIdx.z == 0)      W = Wq;
    else if (blockIdx.z == 1) W = Wk;
    else                      W = Wv;

    const int tid = threadIdx.x;
    const int m0 = blockIdx.y * 64;
    const int n0 = blockIdx.x * 64;
    const int tx = tid & 15;
    const int ty = tid >> 4;
    const int lr = tid >> 2;
    const int lc = (tid & 3) * 4;

    float acc[4][4];
#pragma unroll
    for (int i = 0; i < 4; i++)
#pragma unroll
        for (int j = 0; j < 4; j++) acc[i][j] = 0.f;

    for (int k0 = 0; k0 < DD; k0 += 16) {
        float4 av = *(const float4*)(x + (size_t)(m0 + lr) * DD + k0 + lc);
        float4 bv = *(const float4*)(W + (size_t)(n0 + lr) * DD + k0 + lc);
        __syncthreads();
        As[lc + 0][lr] = av.x; As[lc + 1][lr] = av.y;
        As[lc + 2][lr] = av.z; As[lc + 3][lr] = av.w;
        Bs[lc + 0][lr] = bv.x; Bs[lc + 1][lr] = bv.y;
        Bs[lc + 2][lr] = bv.z; Bs[lc + 3][lr] = bv.w;
        __syncthreads();
#pragma unroll
        for (int kk = 0; kk < 16; kk++) {
            float4 a = *(const float4*)&As[kk][ty * 4];
            float4 b = *(const float4*)&Bs[kk][tx * 4];
            float ar[4] = {a.x, a.y, a.z, a.w};
            float br[4] = {b.x, b.y, b.z, b.w};
#pragma unroll
            for (int i = 0; i < 4; i++)
#pragma unroll
                for (int j = 0; j < 4; j++)
                    acc[i][j] += ar[i] * br[j];
        }
    }

    const int mbase = m0 + ty * 4;
    const int b = mbase >> 12;
    const int nbase = mbase & (NN - 1);

    if (blockIdx.z == 2) {
        // V: store transposed g_vt[(b*H+h)][dh][n], tf32 bits, STG.128 over n
#pragma unroll
        for (int j = 0; j < 4; j++) {
            const int oo = n0 + tx * 4 + j;
            const int h = oo >> 6, dh = oo & 63;
            float4 v;
            v.x = __uint_as_float(f2tf32(acc[0][j]));
            v.y = __uint_as_float(f2tf32(acc[1][j]));
            v.z = __uint_as_float(f2tf32(acc[2][j]));
            v.w = __uint_as_float(f2tf32(acc[3][j]));
            *(float4*)(g_vt + ((size_t)(b * HH + h) * DH + dh) * NN + nbase) = v;
        }
    } else {
        float* out = (blockIdx.z == 0) ? g_q : g_k;
        const float sc = (blockIdx.z == 0) ? (SCALE_F * LOG2E_F) : 1.f;
#pragma unroll
        for (int i = 0; i < 4; i++) {
            const int n = nbase + i;
#pragma unroll
            for (int j = 0; j < 4; j++) {
                const int oo = n0 + tx * 4 + j;
                const int h = oo >> 6, dd = oo & 63;
                out[(((size_t)(b * HH + h) * NN) + n) * DH + dd] =
                    __uint_as_float(f2tf32(acc[i][j] * sc));
            }
        }
    }
}

__global__ __launch_bounds__(256) void gemm_out_kernel(
    const float* __restrict__ Wo,
    const float* __restrict__ bo,
    float* __restrict__ out)
{
    __shared__ float As[16][68];
    __shared__ float Bs[16][68];

    const float* A = g_attn;
    const int tid = threadIdx.x;
    const int m0 = blockIdx.y * 64;
    const int n0 = blockIdx.x * 64;
    const int tx = tid & 15;
    const int ty = tid >> 4;
    const int lr = tid >> 2;
    const int lc = (tid & 3) * 4;

    float acc[4][4];
#pragma unroll
    for (int i = 0; i < 4; i++)
#pragma unroll
        for (int j = 0; j < 4; j++) acc[i][j] = 0.f;

    for (int k0 = 0; k0 < DD; k0 += 16) {
        float4 av = *(const float4*)(A  + (size_t)(m0 + lr) * DD + k0 + lc);
        float4 bv = *(const float4*)(Wo + (size_t)(n0 + lr) * DD + k0 + lc);
        __syncthreads();
        As[lc + 0][lr] = av.x; As[lc + 1][lr] = av.y;
        As[lc + 2][lr] = av.z; As[lc + 3][lr] = av.w;
        Bs[lc + 0][lr] = bv.x; Bs[lc + 1][lr] = bv.y;
        Bs[lc + 2][lr] = bv.z; Bs[lc + 3][lr] = bv.w;
        __syncthreads();
#pragma unroll
        for (int kk = 0; kk < 16; kk++) {
            float4 a = *(const float4*)&As[kk][ty * 4];
            float4 b = *(const float4*)&Bs[kk][tx * 4];
            float ar[4] = {a.x, a.y, a.z, a.w};
            float br[4] = {b.x, b.y, b.z, b.w};
#pragma unroll
            for (int i = 0; i < 4; i++)
#pragma unroll
                for (int j = 0; j < 4; j++)
                    acc[i][j] += ar[i] * br[j];
        }
    }

#pragma unroll
    for (int i = 0; i < 4; i++) {
        const int mm = m0 + ty * 4 + i;
#pragma unroll
        for (int j = 0; j < 4; j++) {
            const int oo = n0 + tx * 4 + j;
            out[(size_t)mm * DD + oo] = acc[i][j] + bo[oo];
        }
    }
}

// ===========================================================================

extern "C" void kernel_launch(void* const* d_in, const int* in_sizes, int n_in,
                              void* d_out, int out_size)
{
    (void)in_sizes; (void)n_in; (void)out_size;
    const float* x  = (const float*)d_in[0];
    const float* Wq = (const float*)d_in[1];
    const float* Wk = (const float*)d_in[2];
    const float* Wv = (const float*)d_in[3];
    const float* Wo = (const float*)d_in[4];
    const float* bo = (const float*)d_in[5];
    float* out = (float*)d_out;

    cudaFuncSetAttribute(attn_mma_kernel,
                         cudaFuncAttributeMaxDynamicSharedMemorySize, SM_TOT);

    gemm_qkv_kernel<<<dim3(DD / 64, (BB * NN) / 64, 3), 256>>>(x, Wq, Wk, Wv);
    attn_mma_kernel<<<dim3(NN / 128, BB * HH), 256, SM_TOT>>>();
    gemm_out_kernel<<<dim3(DD / 64, (BB * NN) / 64), 256>>>(Wo, bo, out);
}

// round 5
// speedup vs baseline: 3.7702x; 1.8039x over previous
#include <cuda_runtime.h>
#include <cuda_fp16.h>
#include <cstdint>
#include <cstddef>

// Problem constants
#define BB 2
#define NN 4096
#define DD 512
#define HH 8
#define DH 64
#define SCALE_F 0.125f   // 64^-0.5
#define LOG2E_F 1.4426950408889634f

// Scratch (allocation-free rule: __device__ globals)
// g_qh: [B*H][N][64] half, pre-scaled by SCALE*LOG2E
// g_kh: [B*H][N][64] half
// g_vth:[B*H][64][N] half (V transposed)
__device__ __half g_qh [(size_t)BB * HH * NN * DH];
__device__ __half g_kh [(size_t)BB * HH * NN * DH];
__device__ __half g_vth[(size_t)BB * HH * NN * DH];
__device__ float  g_attn[(size_t)BB * NN * DD];       // [B,N,512]

// ===========================================================================
// Helpers (arch-neutral PTX only — harness compiles via compute_103, no 'a')
// ===========================================================================

__device__ __forceinline__ uint32_t smem_u32(const void* p) {
    uint32_t a;
    asm("{ .reg .u64 t; cvta.to.shared.u64 t, %1; cvt.u32.u64 %0, t; }"
        : "=r"(a) : "l"(p));
    return a;
}

__device__ __forceinline__ float ex2f(float x) {
    float y;
    asm("ex2.approx.ftz.f32 %0, %1;" : "=f"(y) : "f"(x));
    return y;
}

// D += A @ B   (m16n8k16, f16 in, f32 accum)
__device__ __forceinline__ void mma_f16(float* d, const uint32_t* a, const uint32_t* b) {
    asm volatile(
        "mma.sync.aligned.m16n8k16.row.col.f32.f16.f16.f32 "
        "{%0,%1,%2,%3}, {%4,%5,%6,%7}, {%8,%9}, {%0,%1,%2,%3};"
        : "+f"(d[0]), "+f"(d[1]), "+f"(d[2]), "+f"(d[3])
        : "r"(a[0]), "r"(a[1]), "r"(a[2]), "r"(a[3]), "r"(b[0]), "r"(b[1]));
}

__device__ __forceinline__ void cp_async16(uint32_t dst, const void* src) {
    asm volatile("cp.async.cg.shared.global [%0], [%1], 16;"
                 :: "r"(dst), "l"(src) : "memory");
}
#define CP_COMMIT() asm volatile("cp.async.commit_group;" ::: "memory")
#define CP_WAIT0()  asm volatile("cp.async.wait_group 0;" ::: "memory")

// packed exp2 of (x,y) -> fp16x2 bits
__device__ __forceinline__ uint32_t h2e(float x, float y) {
    __half2 h = h2exp2(__floats2half2_rn(x, y));
    return *(uint32_t*)&h;
}

// ===========================================================================
// Flash attention, fp16 m16n8k16 mma, cp.async double-buffered K/V^T tiles.
// CTA: 128 q rows of one (b,h), 8 warps (16 rows each), kv tiles of 64 keys.
// smem: sK[2][64 rows][128B], sVT[2][64 rows][128B] = 32KB, XOR-swizzled 16B chunks.
// B-frag LDS address (both K and V^T tiles):
//   row*128 + ((chunk ^ (row&7))<<4) + (lane&3)*4, chunk = 2*kstep (+1 for b1)
// ===========================================================================

#define SM_TOT 32768

__global__ void __launch_bounds__(256, 2) attn_mma_kernel()
{
    extern __shared__ char smem[];
    const uint32_t sbase = smem_u32(smem);

    const int tid  = threadIdx.x;
    const int lane = tid & 31;
    const int warp = tid >> 5;
    const int bh   = blockIdx.y;
    const int q0   = blockIdx.x * 128;
    const int wrow = warp * 16;
    const int r0   = lane >> 2;     // 0..7
    const int cB   = lane & 3;      // 0..3

    const __half* khg  = g_kh  + (size_t)bh * NN * DH;
    const __half* vthg = g_vth + (size_t)bh * NN * DH;   // [64][4096]

    const int rowL = tid >> 2;      // 0..63 (loader row)
    const int fq   = tid & 3;       // loader chunk base

    // ---- prologue: issue tile 0 ----
    {
        const char* ksrc = (const char*)(khg + (size_t)rowL * DH);
        const char* vsrc = (const char*)(vthg + (size_t)rowL * NN);
        const uint32_t kdst = sbase + rowL * 128;
        const uint32_t vdst = sbase + 16384 + rowL * 128;
        const uint32_t sw = (uint32_t)(rowL & 7);
        cp_async16(kdst + (((uint32_t)fq       ^ sw) << 4), ksrc + fq * 16);
        cp_async16(kdst + (((uint32_t)(fq + 4) ^ sw) << 4), ksrc + (fq + 4) * 16);
        cp_async16(vdst + (((uint32_t)fq       ^ sw) << 4), vsrc + fq * 16);
        cp_async16(vdst + (((uint32_t)(fq + 4) ^ sw) << 4), vsrc + (fq + 4) * 16);
        CP_COMMIT();
    }

    // ---- Q A-fragments straight from gmem (pre-converted half) ----
    uint32_t qa[4][4];
    {
        const __half* qg = g_qh + ((size_t)bh * NN + q0 + wrow + r0) * DH;
#pragma unroll
        for (int s4 = 0; s4 < 4; s4++) {
            qa[s4][0] = *(const uint32_t*)(qg + s4 * 16 + 2 * cB);
            qa[s4][1] = *(const uint32_t*)(qg + 8 * DH + s4 * 16 + 2 * cB);
            qa[s4][2] = *(const uint32_t*)(qg + s4 * 16 + 2 * cB + 8);
            qa[s4][3] = *(const uint32_t*)(qg + 8 * DH + s4 * 16 + 2 * cB + 8);
        }
    }

    float o[8][4];
#pragma unroll
    for (int n = 0; n < 8; n++)
#pragma unroll
        for (int j = 0; j < 4; j++) o[n][j] = 0.f;
    float m0 = -1e30f, m1 = -1e30f, l0 = 0.f, l1 = 0.f;

    const uint32_t ones[2] = {0x3C003C00u, 0x3C003C00u};

    for (int t = 0; t < NN / 64; t++) {
        CP_WAIT0();
        __syncthreads();          // tile t visible; all warps done with t-1

        if (t + 1 < NN / 64) {
            const int buf = (t + 1) & 1;
            const char* ksrc = (const char*)(khg + ((size_t)(t + 1) * 64 + rowL) * DH);
            const char* vsrc = (const char*)(vthg + (size_t)rowL * NN + (t + 1) * 64);
            const uint32_t kdst = sbase + buf * 8192 + rowL * 128;
            const uint32_t vdst = sbase + 16384 + buf * 8192 + rowL * 128;
            const uint32_t sw = (uint32_t)(rowL & 7);
            cp_async16(kdst + (((uint32_t)fq       ^ sw) << 4), ksrc + fq * 16);
            cp_async16(kdst + (((uint32_t)(fq + 4) ^ sw) << 4), ksrc + (fq + 4) * 16);
            cp_async16(vdst + (((uint32_t)fq       ^ sw) << 4), vsrc + fq * 16);
            cp_async16(vdst + (((uint32_t)(fq + 4) ^ sw) << 4), vsrc + (fq + 4) * 16);
            CP_COMMIT();
        }

        const char* sK = smem + (t & 1) * 8192;
        const char* sV = smem + 16384 + (t & 1) * 8192;

        // ---- S = Q @ K^T  (16 x 64 per warp), 4 k-steps ----
        float sc[8][4];
#pragma unroll
        for (int n = 0; n < 8; n++)
#pragma unroll
            for (int j = 0; j < 4; j++) sc[n][j] = 0.f;

#pragma unroll
        for (int s4 = 0; s4 < 4; s4++) {
#pragma unroll
            for (int n = 0; n < 8; n++) {
                const uint32_t row = (uint32_t)(n * 8 + r0);
                const char* base = sK + row * 128 + cB * 4;
                uint32_t b[2];
                b[0] = *(const uint32_t*)(base + ((uint32_t)((2 * s4)     ^ (row & 7)) << 4));
                b[1] = *(const uint32_t*)(base + ((uint32_t)((2 * s4 + 1) ^ (row & 7)) << 4));
                mma_f16(sc[n], qa[s4], b);
            }
        }

        // ---- online softmax (log2 domain) ----
        float mx0 = -1e30f, mx1 = -1e30f;
#pragma unroll
        for (int n = 0; n < 8; n++) {
            mx0 = fmaxf(mx0, fmaxf(sc[n][0], sc[n][1]));
            mx1 = fmaxf(mx1, fmaxf(sc[n][2], sc[n][3]));
        }
        mx0 = fmaxf(mx0, __shfl_xor_sync(0xffffffffu, mx0, 1));
        mx0 = fmaxf(mx0, __shfl_xor_sync(0xffffffffu, mx0, 2));
        mx1 = fmaxf(mx1, __shfl_xor_sync(0xffffffffu, mx1, 1));
        mx1 = fmaxf(mx1, __shfl_xor_sync(0xffffffffu, mx1, 2));

        const float mn0 = fmaxf(m0, mx0);
        const float mn1 = fmaxf(m1, mx1);
        const float a0 = ex2f(m0 - mn0);
        const float a1 = ex2f(m1 - mn1);
        m0 = mn0; m1 = mn1;

#pragma unroll
        for (int n = 0; n < 8; n++) {
            o[n][0] *= a0; o[n][1] *= a0;
            o[n][2] *= a1; o[n][3] *= a1;
        }

        // ---- P (fp16, in registers) ; O += P @ V ; l via ones-mma ----
        float ls[4] = {0.f, 0.f, 0.f, 0.f};
#pragma unroll
        for (int s4 = 0; s4 < 4; s4++) {
            uint32_t pa[4];
            pa[0] = h2e(sc[2 * s4][0]     - m0, sc[2 * s4][1]     - m0);
            pa[1] = h2e(sc[2 * s4][2]     - m1, sc[2 * s4][3]     - m1);
            pa[2] = h2e(sc[2 * s4 + 1][0] - m0, sc[2 * s4 + 1][1] - m0);
            pa[3] = h2e(sc[2 * s4 + 1][2] - m1, sc[2 * s4 + 1][3] - m1);
            mma_f16(ls, pa, ones);
#pragma unroll
            for (int n = 0; n < 8; n++) {
                const uint32_t row = (uint32_t)(n * 8 + r0);
                const char* base = sV + row * 128 + cB * 4;
                uint32_t b[2];
                b[0] = *(const uint32_t*)(base + ((uint32_t)((2 * s4)     ^ (row & 7)) << 4));
                b[1] = *(const uint32_t*)(base + ((uint32_t)((2 * s4 + 1) ^ (row & 7)) << 4));
                mma_f16(o[n], pa, b);
            }
        }
        l0 = l0 * a0 + ls[0];
        l1 = l1 * a1 + ls[2];
    }

    // ---- epilogue: normalize, write g_attn[b, n, h*64 + :] ----
    const float inv0 = 1.f / l0;
    const float inv1 = 1.f / l1;
    const int b = bh >> 3, h = bh & 7;
    const int row0 = q0 + wrow + r0;
    float* out0 = g_attn + ((size_t)(b * NN + row0)) * DD + h * DH;
    float* out1 = out0 + (size_t)8 * DD;
#pragma unroll
    for (int n = 0; n < 8; n++) {
        const int col = n * 8 + 2 * cB;
        float2 v0; v0.x = o[n][0] * inv0; v0.y = o[n][1] * inv0;
        float2 v1; v1.x = o[n][2] * inv1; v1.y = o[n][3] * inv1;
        *(float2*)(out0 + col) = v0;
        *(float2*)(out1 + col) = v1;
    }
}

// ===========================================================================
// Scalar projection GEMMs; qkv epilogue emits half (Q pre-scaled, V^T).
// ===========================================================================

__global__ __launch_bounds__(256) void gemm_qkv_kernel(
    const float* __restrict__ x,
    const float* __restrict__ Wq,
    const float* __restrict__ Wk,
    const float* __restrict__ Wv)
{
    __shared__ float As[16][68];
    __shared__ float Bs[16][68];

    const float* W;
    if (blockIdx.z == 0)      W = Wq;
    else if (blockIdx.z == 1) W = Wk;
    else                      W = Wv;

    const int tid = threadIdx.x;
    const int m0 = blockIdx.y * 64;
    const int n0 = blockIdx.x * 64;
    const int tx = tid & 15;
    const int ty = tid >> 4;
    const int lr = tid >> 2;
    const int lc = (tid & 3) * 4;

    float acc[4][4];
#pragma unroll
    for (int i = 0; i < 4; i++)
#pragma unroll
        for (int j = 0; j < 4; j++) acc[i][j] = 0.f;

    for (int k0 = 0; k0 < DD; k0 += 16) {
        float4 av = *(const float4*)(x + (size_t)(m0 + lr) * DD + k0 + lc);
        float4 bv = *(const float4*)(W + (size_t)(n0 + lr) * DD + k0 + lc);
        __syncthreads();
        As[lc + 0][lr] = av.x; As[lc + 1][lr] = av.y;
        As[lc + 2][lr] = av.z; As[lc + 3][lr] = av.w;
        Bs[lc + 0][lr] = bv.x; Bs[lc + 1][lr] = bv.y;
        Bs[lc + 2][lr] = bv.z; Bs[lc + 3][lr] = bv.w;
        __syncthreads();
#pragma unroll
        for (int kk = 0; kk < 16; kk++) {
            float4 a = *(const float4*)&As[kk][ty * 4];
            float4 b = *(const float4*)&Bs[kk][tx * 4];
            float ar[4] = {a.x, a.y, a.z, a.w};
            float br[4] = {b.x, b.y, b.z, b.w};
#pragma unroll
            for (int i = 0; i < 4; i++)
#pragma unroll
                for (int j = 0; j < 4; j++)
                    acc[i][j] += ar[i] * br[j];
        }
    }

    const int mbase = m0 + ty * 4;
    const int b = mbase >> 12;
    const int nbase = mbase & (NN - 1);

    if (blockIdx.z == 2) {
        // V: transposed g_vth[(b*H+h)*64 + dh][n], 4 halfs along n per j
#pragma unroll
        for (int j = 0; j < 4; j++) {
            const int oo = n0 + tx * 4 + j;
            const int h = oo >> 6, dh = oo & 63;
            __half2 h01 = __floats2half2_rn(acc[0][j], acc[1][j]);
            __half2 h23 = __floats2half2_rn(acc[2][j], acc[3][j]);
            uint2 pk;
            pk.x = *(uint32_t*)&h01;
            pk.y = *(uint32_t*)&h23;
            *(uint2*)(g_vth + ((size_t)(b * HH + h) * DH + dh) * NN + nbase) = pk;
        }
    } else {
        __half* out = (blockIdx.z == 0) ? g_qh : g_kh;
        const float sc = (blockIdx.z == 0) ? (SCALE_F * LOG2E_F) : 1.f;
#pragma unroll
        for (int i = 0; i < 4; i++) {
            const int n = nbase + i;
#pragma unroll
            for (int j = 0; j < 4; j++) {
                const int oo = n0 + tx * 4 + j;
                const int h = oo >> 6, dd = oo & 63;
                out[(((size_t)(b * HH + h) * NN) + n) * DH + dd] =
                    __float2half(acc[i][j] * sc);
            }
        }
    }
}

__global__ __launch_bounds__(256) void gemm_out_kernel(
    const float* __restrict__ Wo,
    const float* __restrict__ bo,
    float* __restrict__ out)
{
    __shared__ float As[16][68];
    __shared__ float Bs[16][68];

    const float* A = g_attn;
    const int tid = threadIdx.x;
    const int m0 = blockIdx.y * 64;
    const int n0 = blockIdx.x * 64;
    const int tx = tid & 15;
    const int ty = tid >> 4;
    const int lr = tid >> 2;
    const int lc = (tid & 3) * 4;

    float acc[4][4];
#pragma unroll
    for (int i = 0; i < 4; i++)
#pragma unroll
        for (int j = 0; j < 4; j++) acc[i][j] = 0.f;

    for (int k0 = 0; k0 < DD; k0 += 16) {
        float4 av = *(const float4*)(A  + (size_t)(m0 + lr) * DD + k0 + lc);
        float4 bv = *(const float4*)(Wo + (size_t)(n0 + lr) * DD + k0 + lc);
        __syncthreads();
        As[lc + 0][lr] = av.x; As[lc + 1][lr] = av.y;
        As[lc + 2][lr] = av.z; As[lc + 3][lr] = av.w;
        Bs[lc + 0][lr] = bv.x; Bs[lc + 1][lr] = bv.y;
        Bs[lc + 2][lr] = bv.z; Bs[lc + 3][lr] = bv.w;
        __syncthreads();
#pragma unroll
        for (int kk = 0; kk < 16; kk++) {
            float4 a = *(const float4*)&As[kk][ty * 4];
            float4 b = *(const float4*)&Bs[kk][tx * 4];
            float ar[4] = {a.x, a.y, a.z, a.w};
            float br[4] = {b.x, b.y, b.z, b.w};
#pragma unroll
            for (int i = 0; i < 4; i++)
#pragma unroll
                for (int j = 0; j < 4; j++)
                    acc[i][j] += ar[i] * br[j];
        }
    }

#pragma unroll
    for (int i = 0; i < 4; i++) {
        const int mm = m0 + ty * 4 + i;
#pragma unroll
        for (int j = 0; j < 4; j++) {
            const int oo = n0 + tx * 4 + j;
            out[(size_t)mm * DD + oo] = acc[i][j] + bo[oo];
        }
    }
}

// ===========================================================================

extern "C" void kernel_launch(void* const* d_in, const int* in_sizes, int n_in,
                              void* d_out, int out_size)
{
    (void)in_sizes; (void)n_in; (void)out_size;
    const float* x  = (const float*)d_in[0];
    const float* Wq = (const float*)d_in[1];
    const float* Wk = (const float*)d_in[2];
    const float* Wv = (const float*)d_in[3];
    const float* Wo = (const float*)d_in[4];
    const float* bo = (const float*)d_in[5];
    float* out = (float*)d_out;

    cudaFuncSetAttribute(attn_mma_kernel,
                         cudaFuncAttributeMaxDynamicSharedMemorySize, SM_TOT);

    gemm_qkv_kernel<<<dim3(DD / 64, (BB * NN) / 64, 3), 256>>>(x, Wq, Wk, Wv);
    attn_mma_kernel<<<dim3(NN / 128, BB * HH), 256, SM_TOT>>>();
    gemm_out_kernel<<<dim3(DD / 64, (BB * NN) / 64), 256>>>(Wo, bo, out);
}

// round 9
// speedup vs baseline: 6.2530x; 1.6585x over previous
#include <cuda_runtime.h>
#include <cuda_fp16.h>
#include <cstdint>
#include <cstddef>

// Problem constants
#define BB 2
#define NN 4096
#define DD 512
#define HH 8
#define DH 64
#define SCALE_F 0.125f   // 64^-0.5
#define LOG2E_F 1.4426950408889634f

// Scratch (allocation-free rule: __device__ globals).
// NOTE: __device__ symbols must ONLY be referenced from device code —
// passing them as host-side kernel args gives the host shadow address
// (root cause of R6-R8 failures).
__device__ __align__(16) __half g_xh[(size_t)BB * NN * DD];        // x hi  [8192][512]
__device__ __align__(16) __half g_xl[(size_t)BB * NN * DD];        // x lo
__device__ __align__(16) __half g_wh[(size_t)4 * DD * DD];         // Wq,Wk,Wv,Wo hi
__device__ __align__(16) __half g_wl[(size_t)4 * DD * DD];         // lo
__device__ __align__(16) __half g_qh [(size_t)BB * HH * NN * DH];  // [bh][n][64] prescaled
__device__ __align__(16) __half g_kh [(size_t)BB * HH * NN * DH];  // [bh][n][64]
__device__ __align__(16) __half g_vth[(size_t)BB * HH * NN * DH];  // [bh][64][n] (V^T)
__device__ __align__(16) __half g_ah[(size_t)BB * NN * DD];        // attn out hi
__device__ __align__(16) __half g_al[(size_t)BB * NN * DD];        // attn out lo

// ===========================================================================
// Helpers (arch-neutral PTX only)
// ===========================================================================

__device__ __forceinline__ uint32_t smem_u32(const void* p) {
    uint32_t a;
    asm("{ .reg .u64 t; cvta.to.shared.u64 t, %1; cvt.u32.u64 %0, t; }"
        : "=r"(a) : "l"(p));
    return a;
}

__device__ __forceinline__ float ex2f(float x) {
    float y;
    asm("ex2.approx.ftz.f32 %0, %1;" : "=f"(y) : "f"(x));
    return y;
}

__device__ __forceinline__ void mma_f16(float* d, const uint32_t* a, const uint32_t* b) {
    asm volatile(
        "mma.sync.aligned.m16n8k16.row.col.f32.f16.f16.f32 "
        "{%0,%1,%2,%3}, {%4,%5,%6,%7}, {%8,%9}, {%0,%1,%2,%3};"
        : "+f"(d[0]), "+f"(d[1]), "+f"(d[2]), "+f"(d[3])
        : "r"(a[0]), "r"(a[1]), "r"(a[2]), "r"(a[3]), "r"(b[0]), "r"(b[1]));
}

__device__ __forceinline__ void cp_async16(uint32_t dst, const void* src) {
    asm volatile("cp.async.cg.shared.global [%0], [%1], 16;"
                 :: "r"(dst), "l"(src) : "memory");
}
#define CP_COMMIT() asm volatile("cp.async.commit_group;" ::: "memory")
#define CP_WAIT0()  asm volatile("cp.async.wait_group 0;" ::: "memory")

__device__ __forceinline__ uint32_t h2e(float x, float y) {
    __half2 h = h2exp2(__floats2half2_rn(x, y));
    return *(uint32_t*)&h;
}

__device__ __forceinline__ uint32_t pack2(__half a, __half b) {
    __half2 h = __halves2half2(a, b);
    return *(uint32_t*)&h;
}

// split pair of floats into hi/lo fp16x2 words
__device__ __forceinline__ void split2(float a, float b, uint32_t& hi, uint32_t& lo) {
    __half ha = __float2half_rn(a), hb = __float2half_rn(b);
    hi = pack2(ha, hb);
    __half2 L = __floats2half2_rn(a - __half2float(ha), b - __half2float(hb));
    lo = *(uint32_t*)&L;
}

// XOR-swizzled LDS.32 from [row][64-half = 128B] tile
__device__ __forceinline__ uint32_t lds32(const char* base, uint32_t row, uint32_t chunk, uint32_t cB) {
    return *(const uint32_t*)(base + row * 128 + ((chunk ^ (row & 7u)) << 4) + cB * 4);
}

// ===========================================================================
// conversion kernel: fp32 -> (hi, lo) fp16.
// Destination resolved IN DEVICE CODE via `which` (0=x, 1..4=Wq,Wk,Wv,Wo).
// ===========================================================================
__global__ __launch_bounds__(256) void conv_kernel(
    const float* __restrict__ src, int which, int n4)
{
    int idx = blockIdx.x * 256 + threadIdx.x;
    if (idx >= n4) return;

    __half* dh;
    __half* dl;
    if (which == 0) { dh = g_xh; dl = g_xl; }
    else {
        const size_t off = (size_t)(which - 1) * DD * DD;
        dh = g_wh + off; dl = g_wl + off;
    }

    float4 f = ((const float4*)src)[idx];
    uint32_t h0, l0, h1, l1;
    split2(f.x, f.y, h0, l0);
    split2(f.z, f.w, h1, l1);
    uint32_t* dh32 = (uint32_t*)dh;
    uint32_t* dl32 = (uint32_t*)dl;
    dh32[idx * 2 + 0] = h0;
    dh32[idx * 2 + 1] = h1;
    dl32[idx * 2 + 0] = l0;
    dl32[idx * 2 + 1] = l1;
}

// ===========================================================================
// Split-fp16 GEMM: C[128x128 per CTA] = A @ B^T with A=Ah+Al, B=Bh+Bl.
// C ≈ Ah·Bh + Al·Bh + Ah·Bl  (Al·Bl dropped, ~2^-22)
// modes: z=0 Q, z=1 K, z=2 V^T (A/B roles swapped), z=3 out-proj.
// smem: 2 stages x 4 tiles x [128 rows][128B] = 128KB
// ===========================================================================

#define GEMM_SMEM 131072

__global__ __launch_bounds__(256) void hgemm_kernel(
    int mode_arg, const float* __restrict__ bo, float* __restrict__ outp)
{
    extern __shared__ char smem[];
    const uint32_t sbase = smem_u32(smem);

    const int tid  = threadIdx.x;
    const int lane = tid & 31;
    const int warp = tid >> 5;
    const int r0   = lane >> 2;
    const int cB   = lane & 3;
    const int wm   = (warp >> 1) * 32;
    const int wn   = (warp & 1) * 64;
    const int bx   = blockIdx.x;   // 0..3
    const int by   = blockIdx.y;   // 0..63
    const int z    = (mode_arg < 0) ? (int)blockIdx.z : mode_arg;

    const __half *pa_h, *pa_l, *pb_h, *pb_l;
    size_t arow0, brow0;
    if (z == 0)      { pa_h = g_xh; pa_l = g_xl; pb_h = g_wh;              pb_l = g_wl;              arow0 = (size_t)by * 128; brow0 = (size_t)bx * 128; }
    else if (z == 1) { pa_h = g_xh; pa_l = g_xl; pb_h = g_wh + 262144;     pb_l = g_wl + 262144;     arow0 = (size_t)by * 128; brow0 = (size_t)bx * 128; }
    else if (z == 2) { pa_h = g_wh + 2 * 262144; pa_l = g_wl + 2 * 262144; pb_h = g_xh; pb_l = g_xl; arow0 = (size_t)bx * 128; brow0 = (size_t)by * 128; }
    else             { pa_h = g_ah; pa_l = g_al; pb_h = g_wh + 3 * 262144; pb_l = g_wl + 3 * 262144; arow0 = (size_t)by * 128; brow0 = (size_t)bx * 128; }

    const int lrow = tid >> 1;             // 0..127
    const int c0l  = (tid & 1) * 4;        // chunk base: 0 or 4 (4 chunks each)

    // loader for one stage: full 128B per row across the 2 threads per row
    auto issue = [&](int stage, int k0) {
        const uint32_t sw = ((uint32_t)lrow & 7u);
        const uint32_t rowoff = (uint32_t)lrow * 128u;
        const uint32_t st = sbase + stage * 65536;
        const __half* srcs[4] = {
            pa_h + (arow0 + lrow) * DD + k0,
            pa_l + (arow0 + lrow) * DD + k0,
            pb_h + (brow0 + lrow) * DD + k0,
            pb_l + (brow0 + lrow) * DD + k0 };
#pragma unroll
        for (int tile = 0; tile < 4; tile++) {
            const uint32_t tbase = st + tile * 16384 + rowoff;
#pragma unroll
            for (int i = 0; i < 4; i++) {
                const uint32_t c = (uint32_t)(c0l + i);
                cp_async16(tbase + ((c ^ sw) << 4), srcs[tile] + c * 8);
            }
        }
    };

    float acc[2][8][4];
#pragma unroll
    for (int mf = 0; mf < 2; mf++)
#pragma unroll
        for (int nf = 0; nf < 8; nf++)
#pragma unroll
            for (int j = 0; j < 4; j++) acc[mf][nf][j] = 0.f;

    issue(0, 0);
    CP_COMMIT();

    for (int kc = 0; kc < 8; kc++) {
        CP_WAIT0();
        __syncthreads();
        if (kc + 1 < 8) { issue((kc + 1) & 1, (kc + 1) * 64); CP_COMMIT(); }

        const char* sAh = smem + (kc & 1) * 65536;
        const char* sAl = sAh + 16384;
        const char* sBh = sAh + 32768;
        const char* sBl = sAh + 49152;

#pragma unroll
        for (int ks = 0; ks < 4; ks++) {
            uint32_t ah[2][4], al[2][4], wh[8][2], wl[8][2];
#pragma unroll
            for (int mf = 0; mf < 2; mf++) {
                const uint32_t ra = (uint32_t)(wm + mf * 16 + r0);
                ah[mf][0] = lds32(sAh, ra,     2 * ks,     cB);
                ah[mf][1] = lds32(sAh, ra + 8, 2 * ks,     cB);
                ah[mf][2] = lds32(sAh, ra,     2 * ks + 1, cB);
                ah[mf][3] = lds32(sAh, ra + 8, 2 * ks + 1, cB);
                al[mf][0] = lds32(sAl, ra,     2 * ks,     cB);
                al[mf][1] = lds32(sAl, ra + 8, 2 * ks,     cB);
                al[mf][2] = lds32(sAl, ra,     2 * ks + 1, cB);
                al[mf][3] = lds32(sAl, ra + 8, 2 * ks + 1, cB);
            }
#pragma unroll
            for (int nf = 0; nf < 8; nf++) {
                const uint32_t rb = (uint32_t)(wn + nf * 8 + r0);
                wh[nf][0] = lds32(sBh, rb, 2 * ks,     cB);
                wh[nf][1] = lds32(sBh, rb, 2 * ks + 1, cB);
                wl[nf][0] = lds32(sBl, rb, 2 * ks,     cB);
                wl[nf][1] = lds32(sBl, rb, 2 * ks + 1, cB);
            }
#pragma unroll
            for (int mf = 0; mf < 2; mf++)
#pragma unroll
                for (int nf = 0; nf < 8; nf++)
                    mma_f16(acc[mf][nf], ah[mf], wh[nf]);
#pragma unroll
            for (int mf = 0; mf < 2; mf++)
#pragma unroll
                for (int nf = 0; nf < 8; nf++)
                    mma_f16(acc[mf][nf], al[mf], wh[nf]);
#pragma unroll
            for (int mf = 0; mf < 2; mf++)
#pragma unroll
                for (int nf = 0; nf < 8; nf++)
                    mma_f16(acc[mf][nf], ah[mf], wl[nf]);
        }
    }

    // ---- epilogue ----
    if (z == 0 || z == 1) {
        __half* outq = (z == 0) ? g_qh : g_kh;
        const float sc = (z == 0) ? (SCALE_F * LOG2E_F) : 1.f;
#pragma unroll
        for (int mf = 0; mf < 2; mf++) {
            const int tokA = by * 128 + wm + mf * 16 + r0;
#pragma unroll
            for (int nf = 0; nf < 8; nf++) {
                const int oo = bx * 128 + wn + nf * 8 + 2 * cB;
                const int h = oo >> 6, dd = oo & 63;
#pragma unroll
                for (int half_ = 0; half_ < 2; half_++) {
                    const int tok = tokA + half_ * 8;
                    const int b = tok >> 12, n = tok & (NN - 1);
                    const float v0 = acc[mf][nf][2 * half_ + 0] * sc;
                    const float v1 = acc[mf][nf][2 * half_ + 1] * sc;
                    *(uint32_t*)(outq + (((size_t)(b * HH + h) * NN) + n) * DH + dd) =
                        pack2(__float2half_rn(v0), __float2half_rn(v1));
                }
            }
        }
    } else if (z == 2) {
#pragma unroll
        for (int mf = 0; mf < 2; mf++) {
            const int frA = bx * 128 + wm + mf * 16 + r0;
#pragma unroll
            for (int nf = 0; nf < 8; nf++) {
                const int tk = by * 128 + wn + nf * 8 + 2 * cB;
                const int b = tk >> 12, n = tk & (NN - 1);
#pragma unroll
                for (int half_ = 0; half_ < 2; half_++) {
                    const int fr = frA + half_ * 8;
                    const int h = fr >> 6, dd = fr & 63;
                    const float v0 = acc[mf][nf][2 * half_ + 0];
                    const float v1 = acc[mf][nf][2 * half_ + 1];
                    *(uint32_t*)(g_vth + (((size_t)(b * HH + h) * DH) + dd) * NN + n) =
                        pack2(__float2half_rn(v0), __float2half_rn(v1));
                }
            }
        }
    } else {
#pragma unroll
        for (int mf = 0; mf < 2; mf++) {
            const int tokA = by * 128 + wm + mf * 16 + r0;
#pragma unroll
            for (int nf = 0; nf < 8; nf++) {
                const int oo = bx * 128 + wn + nf * 8 + 2 * cB;
                const float b0 = bo[oo], b1 = bo[oo + 1];
#pragma unroll
                for (int half_ = 0; half_ < 2; half_++) {
                    const int tok = tokA + half_ * 8;
                    float2 v;
                    v.x = acc[mf][nf][2 * half_ + 0] + b0;
                    v.y = acc[mf][nf][2 * half_ + 1] + b1;
                    *(float2*)(outp + (size_t)tok * DD + oo) = v;
                }
            }
        }
    }
}

// ===========================================================================
// Flash attention (R5, proven) — epilogue emits hi/lo fp16 for out-proj.
// ===========================================================================

#define SM_TOT 32768

__global__ void __launch_bounds__(256, 2) attn_mma_kernel()
{
    extern __shared__ char smem[];
    const uint32_t sbase = smem_u32(smem);

    const int tid  = threadIdx.x;
    const int lane = tid & 31;
    const int warp = tid >> 5;
    const int bh   = blockIdx.y;
    const int q0   = blockIdx.x * 128;
    const int wrow = warp * 16;
    const int r0   = lane >> 2;
    const int cB   = lane & 3;

    const __half* khg  = g_kh  + (size_t)bh * NN * DH;
    const __half* vthg = g_vth + (size_t)bh * NN * DH;

    const int rowL = tid >> 2;
    const int fq   = tid & 3;

    {
        const char* ksrc = (const char*)(khg + (size_t)rowL * DH);
        const char* vsrc = (const char*)(vthg + (size_t)rowL * NN);
        const uint32_t kdst = sbase + rowL * 128;
        const uint32_t vdst = sbase + 16384 + rowL * 128;
        const uint32_t sw = (uint32_t)(rowL & 7);
        cp_async16(kdst + (((uint32_t)fq       ^ sw) << 4), ksrc + fq * 16);
        cp_async16(kdst + (((uint32_t)(fq + 4) ^ sw) << 4), ksrc + (fq + 4) * 16);
        cp_async16(vdst + (((uint32_t)fq       ^ sw) << 4), vsrc + fq * 16);
        cp_async16(vdst + (((uint32_t)(fq + 4) ^ sw) << 4), vsrc + (fq + 4) * 16);
        CP_COMMIT();
    }

    uint32_t qa[4][4];
    {
        const __half* qg = g_qh + ((size_t)bh * NN + q0 + wrow + r0) * DH;
#pragma unroll
        for (int s4 = 0; s4 < 4; s4++) {
            qa[s4][0] = *(const uint32_t*)(qg + s4 * 16 + 2 * cB);
            qa[s4][1] = *(const uint32_t*)(qg + 8 * DH + s4 * 16 + 2 * cB);
            qa[s4][2] = *(const uint32_t*)(qg + s4 * 16 + 2 * cB + 8);
            qa[s4][3] = *(const uint32_t*)(qg + 8 * DH + s4 * 16 + 2 * cB + 8);
        }
    }

    float o[8][4];
#pragma unroll
    for (int n = 0; n < 8; n++)
#pragma unroll
        for (int j = 0; j < 4; j++) o[n][j] = 0.f;
    float m0 = -1e30f, m1 = -1e30f, l0 = 0.f, l1 = 0.f;

    const uint32_t ones[2] = {0x3C003C00u, 0x3C003C00u};

    for (int t = 0; t < NN / 64; t++) {
        CP_WAIT0();
        __syncthreads();

        if (t + 1 < NN / 64) {
            const int buf = (t + 1) & 1;
            const char* ksrc = (const char*)(khg + ((size_t)(t + 1) * 64 + rowL) * DH);
            const char* vsrc = (const char*)(vthg + (size_t)rowL * NN + (t + 1) * 64);
            const uint32_t kdst = sbase + buf * 8192 + rowL * 128;
            const uint32_t vdst = sbase + 16384 + buf * 8192 + rowL * 128;
            const uint32_t sw = (uint32_t)(rowL & 7);
            cp_async16(kdst + (((uint32_t)fq       ^ sw) << 4), ksrc + fq * 16);
            cp_async16(kdst + (((uint32_t)(fq + 4) ^ sw) << 4), ksrc + (fq + 4) * 16);
            cp_async16(vdst + (((uint32_t)fq       ^ sw) << 4), vsrc + fq * 16);
            cp_async16(vdst + (((uint32_t)(fq + 4) ^ sw) << 4), vsrc + (fq + 4) * 16);
            CP_COMMIT();
        }

        const char* sK = smem + (t & 1) * 8192;
        const char* sV = smem + 16384 + (t & 1) * 8192;

        float sc[8][4];
#pragma unroll
        for (int n = 0; n < 8; n++)
#pragma unroll
            for (int j = 0; j < 4; j++) sc[n][j] = 0.f;

#pragma unroll
        for (int s4 = 0; s4 < 4; s4++) {
#pragma unroll
            for (int n = 0; n < 8; n++) {
                const uint32_t row = (uint32_t)(n * 8 + r0);
                uint32_t b[2];
                b[0] = lds32(sK, row, 2 * s4,     (uint32_t)cB);
                b[1] = lds32(sK, row, 2 * s4 + 1, (uint32_t)cB);
                mma_f16(sc[n], qa[s4], b);
            }
        }

        float mx0 = -1e30f, mx1 = -1e30f;
#pragma unroll
        for (int n = 0; n < 8; n++) {
            mx0 = fmaxf(mx0, fmaxf(sc[n][0], sc[n][1]));
            mx1 = fmaxf(mx1, fmaxf(sc[n][2], sc[n][3]));
        }
        mx0 = fmaxf(mx0, __shfl_xor_sync(0xffffffffu, mx0, 1));
        mx0 = fmaxf(mx0, __shfl_xor_sync(0xffffffffu, mx0, 2));
        mx1 = fmaxf(mx1, __shfl_xor_sync(0xffffffffu, mx1, 1));
        mx1 = fmaxf(mx1, __shfl_xor_sync(0xffffffffu, mx1, 2));

        const float mn0 = fmaxf(m0, mx0);
        const float mn1 = fmaxf(m1, mx1);
        const float a0 = ex2f(m0 - mn0);
        const float a1 = ex2f(m1 - mn1);
        m0 = mn0; m1 = mn1;

#pragma unroll
        for (int n = 0; n < 8; n++) {
            o[n][0] *= a0; o[n][1] *= a0;
            o[n][2] *= a1; o[n][3] *= a1;
        }

        float ls[4] = {0.f, 0.f, 0.f, 0.f};
#pragma unroll
        for (int s4 = 0; s4 < 4; s4++) {
            uint32_t pa[4];
            pa[0] = h2e(sc[2 * s4][0]     - m0, sc[2 * s4][1]     - m0);
            pa[1] = h2e(sc[2 * s4][2]     - m1, sc[2 * s4][3]     - m1);
            pa[2] = h2e(sc[2 * s4 + 1][0] - m0, sc[2 * s4 + 1][1] - m0);
            pa[3] = h2e(sc[2 * s4 + 1][2] - m1, sc[2 * s4 + 1][3] - m1);
            mma_f16(ls, pa, ones);
#pragma unroll
            for (int n = 0; n < 8; n++) {
                const uint32_t row = (uint32_t)(n * 8 + r0);
                uint32_t b[2];
                b[0] = lds32(sV, row, 2 * s4,     (uint32_t)cB);
                b[1] = lds32(sV, row, 2 * s4 + 1, (uint32_t)cB);
                mma_f16(o[n], pa, b);
            }
        }
        l0 = l0 * a0 + ls[0];
        l1 = l1 * a1 + ls[2];
    }

    // ---- epilogue: normalize, split to hi/lo fp16 for out-proj ----
    const float inv0 = 1.f / l0;
    const float inv1 = 1.f / l1;
    const int b = bh >> 3, h = bh & 7;
    const int row0 = q0 + wrow + r0;
    const size_t off0 = ((size_t)(b * NN + row0)) * DD + h * DH;
    const size_t off1 = off0 + (size_t)8 * DD;
#pragma unroll
    for (int n = 0; n < 8; n++) {
        const int col = n * 8 + 2 * cB;
        uint32_t h0, lo0, h1, lo1;
        split2(o[n][0] * inv0, o[n][1] * inv0, h0, lo0);
        split2(o[n][2] * inv1, o[n][3] * inv1, h1, lo1);
        *(uint32_t*)(g_ah + off0 + col) = h0;
        *(uint32_t*)(g_al + off0 + col) = lo0;
        *(uint32_t*)(g_ah + off1 + col) = h1;
        *(uint32_t*)(g_al + off1 + col) = lo1;
    }
}

// ===========================================================================

extern "C" void kernel_launch(void* const* d_in, const int* in_sizes, int n_in,
                              void* d_out, int out_size)
{
    (void)in_sizes; (void)n_in; (void)out_size;
    const float* x  = (const float*)d_in[0];
    const float* Wq = (const float*)d_in[1];
    const float* Wk = (const float*)d_in[2];
    const float* Wv = (const float*)d_in[3];
    const float* Wo = (const float*)d_in[4];
    const float* bo = (const float*)d_in[5];
    float* out = (float*)d_out;

    cudaFuncSetAttribute(hgemm_kernel,
                         cudaFuncAttributeMaxDynamicSharedMemorySize, GEMM_SMEM);
    cudaFuncSetAttribute(attn_mma_kernel,
                         cudaFuncAttributeMaxDynamicSharedMemorySize, SM_TOT);

    // split conversions (dest resolved inside the kernel via `which`)
    conv_kernel<<<4096, 256>>>(x,  0, (BB * NN * DD) / 4);
    conv_kernel<<<256, 256>>>(Wq, 1, (DD * DD) / 4);
    conv_kernel<<<256, 256>>>(Wk, 2, (DD * DD) / 4);
    conv_kernel<<<256, 256>>>(Wv, 3, (DD * DD) / 4);
    conv_kernel<<<256, 256>>>(Wo, 4, (DD * DD) / 4);

    // QKV projections (tensor cores, split-fp16)
    hgemm_kernel<<<dim3(4, 64, 3), 256, GEMM_SMEM>>>(-1, nullptr, nullptr);
    // Flash attention
    attn_mma_kernel<<<dim3(NN / 128, BB * HH), 256, SM_TOT>>>();
    // Output projection + bias
    hgemm_kernel<<<dim3(4, 64, 1), 256, GEMM_SMEM>>>(3, bo, out);
}

// round 10
// speedup vs baseline: 6.3282x; 1.0120x over previous
#include <cuda_runtime.h>
#include <cuda_fp16.h>
#include <cstdint>
#include <cstddef>

// Problem constants
#define BB 2
#define NN 4096
#define DD 512
#define HH 8
#define DH 64
#define SCALE_F 0.125f   // 64^-0.5
#define LOG2E_F 1.4426950408889634f

// Scratch (allocation-free rule: __device__ globals).
// NOTE: __device__ symbols must ONLY be referenced from device code —
// passing them as host-side kernel args gives the host shadow address.
__device__ __align__(16) __half g_xh[(size_t)BB * NN * DD];        // x hi  [8192][512]
__device__ __align__(16) __half g_xl[(size_t)BB * NN * DD];        // x lo
__device__ __align__(16) __half g_wh[(size_t)4 * DD * DD];         // Wq,Wk,Wv,Wo hi
__device__ __align__(16) __half g_wl[(size_t)4 * DD * DD];         // lo
__device__ __align__(16) __half g_qh [(size_t)BB * HH * NN * DH];  // [bh][n][64] prescaled
__device__ __align__(16) __half g_kh [(size_t)BB * HH * NN * DH];  // [bh][n][64]
__device__ __align__(16) __half g_vth[(size_t)BB * HH * NN * DH];  // [bh][64][n] (V^T)
__device__ __align__(16) __half g_ah[(size_t)BB * NN * DD];        // attn out hi
__device__ __align__(16) __half g_al[(size_t)BB * NN * DD];        // attn out lo

// ===========================================================================
// Helpers (arch-neutral PTX only)
// ===========================================================================

__device__ __forceinline__ uint32_t smem_u32(const void* p) {
    uint32_t a;
    asm("{ .reg .u64 t; cvta.to.shared.u64 t, %1; cvt.u32.u64 %0, t; }"
        : "=r"(a) : "l"(p));
    return a;
}

__device__ __forceinline__ float ex2f(float x) {
    float y;
    asm("ex2.approx.ftz.f32 %0, %1;" : "=f"(y) : "f"(x));
    return y;
}

// D += A @ B, f32 accumulator
__device__ __forceinline__ void mma_f16(float* d, const uint32_t* a, const uint32_t* b) {
    asm volatile(
        "mma.sync.aligned.m16n8k16.row.col.f32.f16.f16.f32 "
        "{%0,%1,%2,%3}, {%4,%5,%6,%7}, {%8,%9}, {%0,%1,%2,%3};"
        : "+f"(d[0]), "+f"(d[1]), "+f"(d[2]), "+f"(d[3])
        : "r"(a[0]), "r"(a[1]), "r"(a[2]), "r"(a[3]), "r"(b[0]), "r"(b[1]));
}

// D += A @ B, f16 accumulator (D = 2x b32 = 4 halves)
__device__ __forceinline__ void mma_f16h(uint32_t* d, const uint32_t* a, const uint32_t* b) {
    asm volatile(
        "mma.sync.aligned.m16n8k16.row.col.f16.f16.f16.f16 "
        "{%0,%1}, {%2,%3,%4,%5}, {%6,%7}, {%0,%1};"
        : "+r"(d[0]), "+r"(d[1])
        : "r"(a[0]), "r"(a[1]), "r"(a[2]), "r"(a[3]), "r"(b[0]), "r"(b[1]));
}

__device__ __forceinline__ void cp_async16(uint32_t dst, const void* src) {
    asm volatile("cp.async.cg.shared.global [%0], [%1], 16;"
                 :: "r"(dst), "l"(src) : "memory");
}
#define CP_COMMIT() asm volatile("cp.async.commit_group;" ::: "memory")
#define CP_WAIT0()  asm volatile("cp.async.wait_group 0;" ::: "memory")

__device__ __forceinline__ uint32_t pack2(__half a, __half b) {
    __half2 h = __halves2half2(a, b);
    return *(uint32_t*)&h;
}

// split pair of floats into hi/lo fp16x2 words
__device__ __forceinline__ void split2(float a, float b, uint32_t& hi, uint32_t& lo) {
    __half ha = __float2half_rn(a), hb = __float2half_rn(b);
    hi = pack2(ha, hb);
    __half2 L = __floats2half2_rn(a - __half2float(ha), b - __half2float(hb));
    lo = *(uint32_t*)&L;
}

// P = exp2(d - m) in half2 domain, returns packed fp16x2 bits
__device__ __forceinline__ uint32_t p_h2(uint32_t d_bits, __half2 m2) {
    __half2 d = *(__half2*)&d_bits;
    __half2 p = h2exp2(__hsub2(d, m2));
    return *(uint32_t*)&p;
}

// XOR-swizzled LDS.32 from [row][64-half = 128B] tile
__device__ __forceinline__ uint32_t lds32(const char* base, uint32_t row, uint32_t chunk, uint32_t cB) {
    return *(const uint32_t*)(base + row * 128 + ((chunk ^ (row & 7u)) << 4) + cB * 4);
}

// ===========================================================================
// conversion kernel: fp32 -> (hi, lo) fp16.  Dest via `which` (device-resolved).
// ===========================================================================
__global__ __launch_bounds__(256) void conv_kernel(
    const float* __restrict__ src, int which, int n4)
{
    int idx = blockIdx.x * 256 + threadIdx.x;
    if (idx >= n4) return;

    __half* dh;
    __half* dl;
    if (which == 0) { dh = g_xh; dl = g_xl; }
    else {
        const size_t off = (size_t)(which - 1) * DD * DD;
        dh = g_wh + off; dl = g_wl + off;
    }

    float4 f = ((const float4*)src)[idx];
    uint32_t h0, l0, h1, l1;
    split2(f.x, f.y, h0, l0);
    split2(f.z, f.w, h1, l1);
    uint32_t* dh32 = (uint32_t*)dh;
    uint32_t* dl32 = (uint32_t*)dl;
    dh32[idx * 2 + 0] = h0;
    dh32[idx * 2 + 1] = h1;
    dl32[idx * 2 + 0] = l0;
    dl32[idx * 2 + 1] = l1;
}

// ===========================================================================
// Split-fp16 GEMM (unchanged from R9 — proven)
// ===========================================================================

#define GEMM_SMEM 131072

__global__ __launch_bounds__(256) void hgemm_kernel(
    int mode_arg, const float* __restrict__ bo, float* __restrict__ outp)
{
    extern __shared__ char smem[];
    const uint32_t sbase = smem_u32(smem);

    const int tid  = threadIdx.x;
    const int lane = tid & 31;
    const int warp = tid >> 5;
    const int r0   = lane >> 2;
    const int cB   = lane & 3;
    const int wm   = (warp >> 1) * 32;
    const int wn   = (warp & 1) * 64;
    const int bx   = blockIdx.x;
    const int by   = blockIdx.y;
    const int z    = (mode_arg < 0) ? (int)blockIdx.z : mode_arg;

    const __half *pa_h, *pa_l, *pb_h, *pb_l;
    size_t arow0, brow0;
    if (z == 0)      { pa_h = g_xh; pa_l = g_xl; pb_h = g_wh;              pb_l = g_wl;              arow0 = (size_t)by * 128; brow0 = (size_t)bx * 128; }
    else if (z == 1) { pa_h = g_xh; pa_l = g_xl; pb_h = g_wh + 262144;     pb_l = g_wl + 262144;     arow0 = (size_t)by * 128; brow0 = (size_t)bx * 128; }
    else if (z == 2) { pa_h = g_wh + 2 * 262144; pa_l = g_wl + 2 * 262144; pb_h = g_xh; pb_l = g_xl; arow0 = (size_t)bx * 128; brow0 = (size_t)by * 128; }
    else             { pa_h = g_ah; pa_l = g_al; pb_h = g_wh + 3 * 262144; pb_l = g_wl + 3 * 262144; arow0 = (size_t)by * 128; brow0 = (size_t)bx * 128; }

    const int lrow = tid >> 1;
    const int c0l  = (tid & 1) * 4;

    auto issue = [&](int stage, int k0) {
        const uint32_t sw = ((uint32_t)lrow & 7u);
        const uint32_t rowoff = (uint32_t)lrow * 128u;
        const uint32_t st = sbase + stage * 65536;
        const __half* srcs[4] = {
            pa_h + (arow0 + lrow) * DD + k0,
            pa_l + (arow0 + lrow) * DD + k0,
            pb_h + (brow0 + lrow) * DD + k0,
            pb_l + (brow0 + lrow) * DD + k0 };
#pragma unroll
        for (int tile = 0; tile < 4; tile++) {
            const uint32_t tbase = st + tile * 16384 + rowoff;
#pragma unroll
            for (int i = 0; i < 4; i++) {
                const uint32_t c = (uint32_t)(c0l + i);
                cp_async16(tbase + ((c ^ sw) << 4), srcs[tile] + c * 8);
            }
        }
    };

    float acc[2][8][4];
#pragma unroll
    for (int mf = 0; mf < 2; mf++)
#pragma unroll
        for (int nf = 0; nf < 8; nf++)
#pragma unroll
            for (int j = 0; j < 4; j++) acc[mf][nf][j] = 0.f;

    issue(0, 0);
    CP_COMMIT();

    for (int kc = 0; kc < 8; kc++) {
        CP_WAIT0();
        __syncthreads();
        if (kc + 1 < 8) { issue((kc + 1) & 1, (kc + 1) * 64); CP_COMMIT(); }

        const char* sAh = smem + (kc & 1) * 65536;
        const char* sAl = sAh + 16384;
        const char* sBh = sAh + 32768;
        const char* sBl = sAh + 49152;

#pragma unroll
        for (int ks = 0; ks < 4; ks++) {
            uint32_t ah[2][4], al[2][4], wh[8][2], wl[8][2];
#pragma unroll
            for (int mf = 0; mf < 2; mf++) {
                const uint32_t ra = (uint32_t)(wm + mf * 16 + r0);
                ah[mf][0] = lds32(sAh, ra,     2 * ks,     cB);
                ah[mf][1] = lds32(sAh, ra + 8, 2 * ks,     cB);
                ah[mf][2] = lds32(sAh, ra,     2 * ks + 1, cB);
                ah[mf][3] = lds32(sAh, ra + 8, 2 * ks + 1, cB);
                al[mf][0] = lds32(sAl, ra,     2 * ks,     cB);
                al[mf][1] = lds32(sAl, ra + 8, 2 * ks,     cB);
                al[mf][2] = lds32(sAl, ra,     2 * ks + 1, cB);
                al[mf][3] = lds32(sAl, ra + 8, 2 * ks + 1, cB);
            }
#pragma unroll
            for (int nf = 0; nf < 8; nf++) {
                const uint32_t rb = (uint32_t)(wn + nf * 8 + r0);
                wh[nf][0] = lds32(sBh, rb, 2 * ks,     cB);
                wh[nf][1] = lds32(sBh, rb, 2 * ks + 1, cB);
                wl[nf][0] = lds32(sBl, rb, 2 * ks,     cB);
                wl[nf][1] = lds32(sBl, rb, 2 * ks + 1, cB);
            }
#pragma unroll
            for (int mf = 0; mf < 2; mf++)
#pragma unroll
                for (int nf = 0; nf < 8; nf++)
                    mma_f16(acc[mf][nf], ah[mf], wh[nf]);
#pragma unroll
            for (int mf = 0; mf < 2; mf++)
#pragma unroll
                for (int nf = 0; nf < 8; nf++)
                    mma_f16(acc[mf][nf], al[mf], wh[nf]);
#pragma unroll
            for (int mf = 0; mf < 2; mf++)
#pragma unroll
                for (int nf = 0; nf < 8; nf++)
                    mma_f16(acc[mf][nf], ah[mf], wl[nf]);
        }
    }

    if (z == 0 || z == 1) {
        __half* outq = (z == 0) ? g_qh : g_kh;
        const float sc = (z == 0) ? (SCALE_F * LOG2E_F) : 1.f;
#pragma unroll
        for (int mf = 0; mf < 2; mf++) {
            const int tokA = by * 128 + wm + mf * 16 + r0;
#pragma unroll
            for (int nf = 0; nf < 8; nf++) {
                const int oo = bx * 128 + wn + nf * 8 + 2 * cB;
                const int h = oo >> 6, dd = oo & 63;
#pragma unroll
                for (int half_ = 0; half_ < 2; half_++) {
                    const int tok = tokA + half_ * 8;
                    const int b = tok >> 12, n = tok & (NN - 1);
                    const float v0 = acc[mf][nf][2 * half_ + 0] * sc;
                    const float v1 = acc[mf][nf][2 * half_ + 1] * sc;
                    *(uint32_t*)(outq + (((size_t)(b * HH + h) * NN) + n) * DH + dd) =
                        pack2(__float2half_rn(v0), __float2half_rn(v1));
                }
            }
        }
    } else if (z == 2) {
#pragma unroll
        for (int mf = 0; mf < 2; mf++) {
            const int frA = bx * 128 + wm + mf * 16 + r0;
#pragma unroll
            for (int nf = 0; nf < 8; nf++) {
                const int tk = by * 128 + wn + nf * 8 + 2 * cB;
                const int b = tk >> 12, n = tk & (NN - 1);
#pragma unroll
                for (int half_ = 0; half_ < 2; half_++) {
                    const int fr = frA + half_ * 8;
                    const int h = fr >> 6, dd = fr & 63;
                    const float v0 = acc[mf][nf][2 * half_ + 0];
                    const float v1 = acc[mf][nf][2 * half_ + 1];
                    *(uint32_t*)(g_vth + (((size_t)(b * HH + h) * DH) + dd) * NN + n) =
                        pack2(__float2half_rn(v0), __float2half_rn(v1));
                }
            }
        }
    } else {
#pragma unroll
        for (int mf = 0; mf < 2; mf++) {
            const int tokA = by * 128 + wm + mf * 16 + r0;
#pragma unroll
            for (int nf = 0; nf < 8; nf++) {
                const int oo = bx * 128 + wn + nf * 8 + 2 * cB;
                const float b0 = bo[oo], b1 = bo[oo + 1];
#pragma unroll
                for (int half_ = 0; half_ < 2; half_++) {
                    const int tok = tokA + half_ * 8;
                    float2 v;
                    v.x = acc[mf][nf][2 * half_ + 0] + b0;
                    v.y = acc[mf][nf][2 * half_ + 1] + b1;
                    *(float2*)(outp + (size_t)tok * DD + oo) = v;
                }
            }
        }
    }
}

// ===========================================================================
// Flash attention: QK in f16-accum (S lands as half2 = PV A-frag layout),
// half2 softmax, guarded rescale. PV/l stay f32-accum.
// ===========================================================================

#define SM_TOT 32768

__global__ void __launch_bounds__(256, 2) attn_mma_kernel()
{
    extern __shared__ char smem[];
    const uint32_t sbase = smem_u32(smem);

    const int tid  = threadIdx.x;
    const int lane = tid & 31;
    const int warp = tid >> 5;
    const int bh   = blockIdx.y;
    const int q0   = blockIdx.x * 128;
    const int wrow = warp * 16;
    const int r0   = lane >> 2;
    const int cB   = lane & 3;

    const __half* khg  = g_kh  + (size_t)bh * NN * DH;
    const __half* vthg = g_vth + (size_t)bh * NN * DH;

    const int rowL = tid >> 2;
    const int fq   = tid & 3;

    {
        const char* ksrc = (const char*)(khg + (size_t)rowL * DH);
        const char* vsrc = (const char*)(vthg + (size_t)rowL * NN);
        const uint32_t kdst = sbase + rowL * 128;
        const uint32_t vdst = sbase + 16384 + rowL * 128;
        const uint32_t sw = (uint32_t)(rowL & 7);
        cp_async16(kdst + (((uint32_t)fq       ^ sw) << 4), ksrc + fq * 16);
        cp_async16(kdst + (((uint32_t)(fq + 4) ^ sw) << 4), ksrc + (fq + 4) * 16);
        cp_async16(vdst + (((uint32_t)fq       ^ sw) << 4), vsrc + fq * 16);
        cp_async16(vdst + (((uint32_t)(fq + 4) ^ sw) << 4), vsrc + (fq + 4) * 16);
        CP_COMMIT();
    }

    uint32_t qa[4][4];
    {
        const __half* qg = g_qh + ((size_t)bh * NN + q0 + wrow + r0) * DH;
#pragma unroll
        for (int s4 = 0; s4 < 4; s4++) {
            qa[s4][0] = *(const uint32_t*)(qg + s4 * 16 + 2 * cB);
            qa[s4][1] = *(const uint32_t*)(qg + 8 * DH + s4 * 16 + 2 * cB);
            qa[s4][2] = *(const uint32_t*)(qg + s4 * 16 + 2 * cB + 8);
            qa[s4][3] = *(const uint32_t*)(qg + 8 * DH + s4 * 16 + 2 * cB + 8);
        }
    }

    float o[8][4];
#pragma unroll
    for (int n = 0; n < 8; n++)
#pragma unroll
        for (int j = 0; j < 4; j++) o[n][j] = 0.f;
    float m0 = -1e30f, m1 = -1e30f, l0 = 0.f, l1 = 0.f;

    const uint32_t ones[2] = {0x3C003C00u, 0x3C003C00u};

    for (int t = 0; t < NN / 64; t++) {
        CP_WAIT0();
        __syncthreads();

        if (t + 1 < NN / 64) {
            const int buf = (t + 1) & 1;
            const char* ksrc = (const char*)(khg + ((size_t)(t + 1) * 64 + rowL) * DH);
            const char* vsrc = (const char*)(vthg + (size_t)rowL * NN + (t + 1) * 64);
            const uint32_t kdst = sbase + buf * 8192 + rowL * 128;
            const uint32_t vdst = sbase + 16384 + buf * 8192 + rowL * 128;
            const uint32_t sw = (uint32_t)(rowL & 7);
            cp_async16(kdst + (((uint32_t)fq       ^ sw) << 4), ksrc + fq * 16);
            cp_async16(kdst + (((uint32_t)(fq + 4) ^ sw) << 4), ksrc + (fq + 4) * 16);
            cp_async16(vdst + (((uint32_t)fq       ^ sw) << 4), vsrc + fq * 16);
            cp_async16(vdst + (((uint32_t)(fq + 4) ^ sw) << 4), vsrc + (fq + 4) * 16);
            CP_COMMIT();
        }

        const char* sK = smem + (t & 1) * 8192;
        const char* sV = smem + 16384 + (t & 1) * 8192;

        // ---- S = Q @ K^T, f16 accumulator.  sc[n][0]=row r0 pair, [1]=row r0+8 ----
        uint32_t sc[8][2];
#pragma unroll
        for (int n = 0; n < 8; n++) { sc[n][0] = 0u; sc[n][1] = 0u; }

#pragma unroll
        for (int s4 = 0; s4 < 4; s4++) {
#pragma unroll
            for (int n = 0; n < 8; n++) {
                const uint32_t row = (uint32_t)(n * 8 + r0);
                uint32_t b[2];
                b[0] = lds32(sK, row, 2 * s4,     (uint32_t)cB);
                b[1] = lds32(sK, row, 2 * s4 + 1, (uint32_t)cB);
                mma_f16h(sc[n], qa[s4], b);
            }
        }

        // ---- online softmax, half2 domain ----
        __half2 hx0 = *(__half2*)&sc[0][0];
        __half2 hx1 = *(__half2*)&sc[0][1];
#pragma unroll
        for (int n = 1; n < 8; n++) {
            hx0 = __hmax2(hx0, *(__half2*)&sc[n][0]);
            hx1 = __hmax2(hx1, *(__half2*)&sc[n][1]);
        }
        float mx0 = fmaxf(__low2float(hx0), __high2float(hx0));
        float mx1 = fmaxf(__low2float(hx1), __high2float(hx1));
        mx0 = fmaxf(mx0, __shfl_xor_sync(0xffffffffu, mx0, 1));
        mx0 = fmaxf(mx0, __shfl_xor_sync(0xffffffffu, mx0, 2));
        mx1 = fmaxf(mx1, __shfl_xor_sync(0xffffffffu, mx1, 1));
        mx1 = fmaxf(mx1, __shfl_xor_sync(0xffffffffu, mx1, 2));

        if (mx0 > m0) {
            const float a0 = ex2f(m0 - mx0);
            l0 *= a0;
#pragma unroll
            for (int n = 0; n < 8; n++) { o[n][0] *= a0; o[n][1] *= a0; }
            m0 = mx0;
        }
        if (mx1 > m1) {
            const float a1 = ex2f(m1 - mx1);
            l1 *= a1;
#pragma unroll
            for (int n = 0; n < 8; n++) { o[n][2] *= a1; o[n][3] *= a1; }
            m1 = mx1;
        }

        const __half2 m0h2 = __floats2half2_rn(m0, m0);
        const __half2 m1h2 = __floats2half2_rn(m1, m1);

        // ---- P = exp2(S - m) (already PV A-frag layout); O += P @ V; l via ones-mma ----
        float ls[4] = {0.f, 0.f, 0.f, 0.f};
#pragma unroll
        for (int s4 = 0; s4 < 4; s4++) {
            uint32_t pa[4];
            pa[0] = p_h2(sc[2 * s4][0],     m0h2);
            pa[1] = p_h2(sc[2 * s4][1],     m1h2);
            pa[2] = p_h2(sc[2 * s4 + 1][0], m0h2);
            pa[3] = p_h2(sc[2 * s4 + 1][1], m1h2);
            mma_f16(ls, pa, ones);
#pragma unroll
            for (int n = 0; n < 8; n++) {
                const uint32_t row = (uint32_t)(n * 8 + r0);
                uint32_t b[2];
                b[0] = lds32(sV, row, 2 * s4,     (uint32_t)cB);
                b[1] = lds32(sV, row, 2 * s4 + 1, (uint32_t)cB);
                mma_f16(o[n], pa, b);
            }
        }
        l0 += ls[0];
        l1 += ls[2];
    }

    // ---- epilogue: normalize, split to hi/lo fp16 for out-proj ----
    const float inv0 = 1.f / l0;
    const float inv1 = 1.f / l1;
    const int b = bh >> 3, h = bh & 7;
    const int row0 = q0 + wrow + r0;
    const size_t off0 = ((size_t)(b * NN + row0)) * DD + h * DH;
    const size_t off1 = off0 + (size_t)8 * DD;
#pragma unroll
    for (int n = 0; n < 8; n++) {
        const int col = n * 8 + 2 * cB;
        uint32_t h0, lo0, h1, lo1;
        split2(o[n][0] * inv0, o[n][1] * inv0, h0, lo0);
        split2(o[n][2] * inv1, o[n][3] * inv1, h1, lo1);
        *(uint32_t*)(g_ah + off0 + col) = h0;
        *(uint32_t*)(g_al + off0 + col) = lo0;
        *(uint32_t*)(g_ah + off1 + col) = h1;
        *(uint32_t*)(g_al + off1 + col) = lo1;
    }
}

// ===========================================================================

extern "C" void kernel_launch(void* const* d_in, const int* in_sizes, int n_in,
                              void* d_out, int out_size)
{
    (void)in_sizes; (void)n_in; (void)out_size;
    const float* x  = (const float*)d_in[0];
    const float* Wq = (const float*)d_in[1];
    const float* Wk = (const float*)d_in[2];
    const float* Wv = (const float*)d_in[3];
    const float* Wo = (const float*)d_in[4];
    const float* bo = (const float*)d_in[5];
    float* out = (float*)d_out;

    cudaFuncSetAttribute(hgemm_kernel,
                         cudaFuncAttributeMaxDynamicSharedMemorySize, GEMM_SMEM);
    cudaFuncSetAttribute(attn_mma_kernel,
                         cudaFuncAttributeMaxDynamicSharedMemorySize, SM_TOT);

    // split conversions (dest resolved inside the kernel via `which`)
    conv_kernel<<<4096, 256>>>(x,  0, (BB * NN * DD) / 4);
    conv_kernel<<<256, 256>>>(Wq, 1, (DD * DD) / 4);
    conv_kernel<<<256, 256>>>(Wk, 2, (DD * DD) / 4);
    conv_kernel<<<256, 256>>>(Wv, 3, (DD * DD) / 4);
    conv_kernel<<<256, 256>>>(Wo, 4, (DD * DD) / 4);

    // QKV projections (tensor cores, split-fp16)
    hgemm_kernel<<<dim3(4, 64, 3), 256, GEMM_SMEM>>>(-1, nullptr, nullptr);
    // Flash attention
    attn_mma_kernel<<<dim3(NN / 128, BB * HH), 256, SM_TOT>>>();
    // Output projection + bias
    hgemm_kernel<<<dim3(4, 64, 1), 256, GEMM_SMEM>>>(3, bo, out);
}